// round 1
// baseline (speedup 1.0000x reference)
#include <cuda_runtime.h>

#define NB 4
#define NS 2048
#define ND 1024
#define NH 16
#define NDK 64
#define NBH (NB*NH)   /* 64 */
#define NM (NB*NS)    /* 8192 */

// Scratch (allocation-free: __device__ globals)
__device__ float g_Q[NBH*NS*NDK];
__device__ float g_K[NBH*NS*NDK];
__device__ float g_V[NBH*NS*NDK];
__device__ float g_ctx[(size_t)NM*ND];
__device__ float g_out[(size_t)NM*ND];
__device__ float g_m[NBH*NS];
__device__ float g_l[NBH*NS];

// ---------------------------------------------------------------------------
// C[m,n] = sum_k A[m,k] * W[n,k] + bias[n]
// MODE 0: C is [M, 1024] flat.
// MODE 1: C is [B,H,S,Dk] head-split, scaled by `scale`.
// BM=BN=128, BK=8, 256 threads, 8x8 per-thread microtile.
// ---------------------------------------------------------------------------
template<int MODE>
__global__ __launch_bounds__(256)
void gemm_xwT(const float* __restrict__ A, const float* __restrict__ W,
              const float* __restrict__ bias, float* __restrict__ C, float scale)
{
    __shared__ float As[8][132];
    __shared__ float Bs[8][132];
    const int tid = threadIdx.x;
    const int tx = tid & 15, ty = tid >> 4;
    const int m0 = blockIdx.y << 7, n0 = blockIdx.x << 7;
    const int lr = tid >> 1, lc = (tid & 1) << 2;

    float acc[8][8];
#pragma unroll
    for (int i = 0; i < 8; i++)
#pragma unroll
        for (int j = 0; j < 8; j++) acc[i][j] = 0.f;

    const float* Ap = A + (size_t)(m0 + lr) * ND + lc;
    const float* Wp = W + (size_t)(n0 + lr) * ND + lc;

    for (int k0 = 0; k0 < ND; k0 += 8) {
        float4 av = *(const float4*)(Ap + k0);
        float4 bv = *(const float4*)(Wp + k0);
        __syncthreads();
        As[lc+0][lr]=av.x; As[lc+1][lr]=av.y; As[lc+2][lr]=av.z; As[lc+3][lr]=av.w;
        Bs[lc+0][lr]=bv.x; Bs[lc+1][lr]=bv.y; Bs[lc+2][lr]=bv.z; Bs[lc+3][lr]=bv.w;
        __syncthreads();
#pragma unroll
        for (int kk = 0; kk < 8; kk++) {
            float a[8], b[8];
            *(float4*)(a)   = *(const float4*)&As[kk][ty*8];
            *(float4*)(a+4) = *(const float4*)&As[kk][ty*8+4];
            *(float4*)(b)   = *(const float4*)&Bs[kk][tx*8];
            *(float4*)(b+4) = *(const float4*)&Bs[kk][tx*8+4];
#pragma unroll
            for (int i = 0; i < 8; i++)
#pragma unroll
                for (int j = 0; j < 8; j++) acc[i][j] += a[i]*b[j];
        }
    }

    const int n = n0 + tx*8;
    float4 bv0 = *(const float4*)&bias[n];
    float4 bv1 = *(const float4*)&bias[n+4];

#pragma unroll
    for (int i = 0; i < 8; i++) {
        int m = m0 + ty*8 + i;
        float4 o0 = make_float4(acc[i][0]+bv0.x, acc[i][1]+bv0.y,
                                acc[i][2]+bv0.z, acc[i][3]+bv0.w);
        float4 o1 = make_float4(acc[i][4]+bv1.x, acc[i][5]+bv1.y,
                                acc[i][6]+bv1.z, acc[i][7]+bv1.w);
        if (MODE == 0) {
            size_t base = (size_t)m * ND + n;
            *(float4*)(C + base)     = o0;
            *(float4*)(C + base + 4) = o1;
        } else {
            int bb = m >> 11;          // / NS
            int ss = m & (NS - 1);
            int h  = n >> 6;           // / NDK
            int d  = n & (NDK - 1);
            size_t base = (((size_t)bb*NH + h)*NS + ss)*NDK + d;
            o0.x *= scale; o0.y *= scale; o0.z *= scale; o0.w *= scale;
            o1.x *= scale; o1.y *= scale; o1.z *= scale; o1.w *= scale;
            *(float4*)(C + base)     = o0;
            *(float4*)(C + base + 4) = o1;
        }
    }
}

// ---------------------------------------------------------------------------
// Attention pass 1: per (bh, q-tile of 64), compute softmax row max m and
// denominator l over causal k-tiles (streaming).
// 256 threads as 16x16; each thread owns a 4x4 piece of the 64x64 score tile.
// ---------------------------------------------------------------------------
__global__ __launch_bounds__(256)
void attn_ml_kernel()
{
    const int qt = blockIdx.x;
    const int bh = blockIdx.y;
    __shared__ float Qs[64][65];
    __shared__ float Ks[64][65];
    __shared__ float m_s[64];
    __shared__ float l_s[64];
    const int tid = threadIdx.x;
    const int tx = tid & 15, ty = tid >> 4;
    const float* Qg = g_Q + ((size_t)bh*NS + qt*64)*NDK;
    const float* Kg = g_K + (size_t)bh*NS*NDK;

#pragma unroll
    for (int u = 0; u < 4; u++) {
        int f = u*256 + tid;
        int r = f >> 4, c = (f & 15) << 2;
        float4 vv = *(const float4*)(Qg + r*NDK + c);
        Qs[r][c]=vv.x; Qs[r][c+1]=vv.y; Qs[r][c+2]=vv.z; Qs[r][c+3]=vv.w;
    }
    if (tid < 64) { m_s[tid] = -3.0e38f; l_s[tid] = 0.f; }
    __syncthreads();

    for (int kt = 0; kt <= qt; kt++) {
#pragma unroll
        for (int u = 0; u < 4; u++) {
            int f = u*256 + tid;
            int r = f >> 4, c = (f & 15) << 2;
            float4 vv = *(const float4*)(Kg + ((size_t)kt*64 + r)*NDK + c);
            Ks[r][c]=vv.x; Ks[r][c+1]=vv.y; Ks[r][c+2]=vv.z; Ks[r][c+3]=vv.w;
        }
        __syncthreads();

        float s[4][4];
#pragma unroll
        for (int i = 0; i < 4; i++)
#pragma unroll
            for (int j = 0; j < 4; j++) s[i][j] = 0.f;

#pragma unroll 8
        for (int d = 0; d < 64; d++) {
            float a[4], b[4];
#pragma unroll
            for (int i = 0; i < 4; i++) a[i] = Qs[ty*4+i][d];
#pragma unroll
            for (int j = 0; j < 4; j++) b[j] = Ks[tx*4+j][d];
#pragma unroll
            for (int i = 0; i < 4; i++)
#pragma unroll
                for (int j = 0; j < 4; j++) s[i][j] += a[i]*b[j];
        }

        if (kt == qt) {
#pragma unroll
            for (int i = 0; i < 4; i++)
#pragma unroll
                for (int j = 0; j < 4; j++)
                    if (ty*4+i < tx*4+j) s[i][j] = -1e30f;
        }

        float rmax[4];
#pragma unroll
        for (int i = 0; i < 4; i++) {
            rmax[i] = fmaxf(fmaxf(s[i][0], s[i][1]), fmaxf(s[i][2], s[i][3]));
#pragma unroll
            for (int o = 8; o > 0; o >>= 1)
                rmax[i] = fmaxf(rmax[i], __shfl_xor_sync(0xffffffffu, rmax[i], o));
        }
        if (tx == 0) {
#pragma unroll
            for (int i = 0; i < 4; i++) {
                int r = ty*4 + i;
                float mo = m_s[r];
                float mn = fmaxf(mo, rmax[i]);
                m_s[r] = mn;
                l_s[r] *= __expf(mo - mn);
            }
        }
        __syncthreads();

        float ps[4];
#pragma unroll
        for (int i = 0; i < 4; i++) {
            float mrow = m_s[ty*4+i];
            ps[i] = __expf(s[i][0]-mrow) + __expf(s[i][1]-mrow)
                  + __expf(s[i][2]-mrow) + __expf(s[i][3]-mrow);
#pragma unroll
            for (int o = 8; o > 0; o >>= 1)
                ps[i] += __shfl_xor_sync(0xffffffffu, ps[i], o);
        }
        if (tx == 0) {
#pragma unroll
            for (int i = 0; i < 4; i++) l_s[ty*4+i] += ps[i];
        }
        __syncthreads();
    }

    if (tid < 64) {
        g_m[(size_t)bh*NS + qt*64 + tid] = m_s[tid];
        g_l[(size_t)bh*NS + qt*64 + tid] = l_s[tid];
    }
}

// ---------------------------------------------------------------------------
// Attention pass 2: recompute scores, p = exp(s-m)/l, write attn (optional),
// accumulate out = P @ V into g_ctx ([B,S,D] layout).
// Dynamic smem: Qs | KPs (K tile, reused for P) | Vs, each 64x65 floats.
// ---------------------------------------------------------------------------
__global__ __launch_bounds__(256)
void attn_av_kernel(float* __restrict__ attn, int write_attn)
{
    extern __shared__ float dyn[];
    float (*Qs)[65]  = (float(*)[65])(dyn);
    float (*KPs)[65] = (float(*)[65])(dyn + 64*65);
    float (*Vs)[65]  = (float(*)[65])(dyn + 2*64*65);
    __shared__ float m_s[64];
    __shared__ float li_s[64];

    const int qt = blockIdx.x;
    const int bh = blockIdx.y;
    const int tid = threadIdx.x;
    const int tx = tid & 15, ty = tid >> 4;
    const float* Qg = g_Q + ((size_t)bh*NS + qt*64)*NDK;
    const float* Kg = g_K + (size_t)bh*NS*NDK;
    const float* Vg = g_V + (size_t)bh*NS*NDK;

#pragma unroll
    for (int u = 0; u < 4; u++) {
        int f = u*256 + tid;
        int r = f >> 4, c = (f & 15) << 2;
        float4 vv = *(const float4*)(Qg + r*NDK + c);
        Qs[r][c]=vv.x; Qs[r][c+1]=vv.y; Qs[r][c+2]=vv.z; Qs[r][c+3]=vv.w;
    }
    if (tid < 64) {
        m_s[tid]  = g_m[(size_t)bh*NS + qt*64 + tid];
        li_s[tid] = 1.0f / g_l[(size_t)bh*NS + qt*64 + tid];
    }
    __syncthreads();

    float o[4][4];
#pragma unroll
    for (int i = 0; i < 4; i++)
#pragma unroll
        for (int j = 0; j < 4; j++) o[i][j] = 0.f;

    for (int kt = 0; kt <= qt; kt++) {
#pragma unroll
        for (int u = 0; u < 4; u++) {
            int f = u*256 + tid;
            int r = f >> 4, c = (f & 15) << 2;
            float4 kv = *(const float4*)(Kg + ((size_t)kt*64 + r)*NDK + c);
            KPs[r][c]=kv.x; KPs[r][c+1]=kv.y; KPs[r][c+2]=kv.z; KPs[r][c+3]=kv.w;
            float4 vv = *(const float4*)(Vg + ((size_t)kt*64 + r)*NDK + c);
            Vs[r][c]=vv.x; Vs[r][c+1]=vv.y; Vs[r][c+2]=vv.z; Vs[r][c+3]=vv.w;
        }
        __syncthreads();

        float s[4][4];
#pragma unroll
        for (int i = 0; i < 4; i++)
#pragma unroll
            for (int j = 0; j < 4; j++) s[i][j] = 0.f;

#pragma unroll 8
        for (int d = 0; d < 64; d++) {
            float a[4], b[4];
#pragma unroll
            for (int i = 0; i < 4; i++) a[i] = Qs[ty*4+i][d];
#pragma unroll
            for (int j = 0; j < 4; j++) b[j] = KPs[tx*4+j][d];
#pragma unroll
            for (int i = 0; i < 4; i++)
#pragma unroll
                for (int j = 0; j < 4; j++) s[i][j] += a[i]*b[j];
        }

        if (kt == qt) {
#pragma unroll
            for (int i = 0; i < 4; i++)
#pragma unroll
                for (int j = 0; j < 4; j++)
                    if (ty*4+i < tx*4+j) s[i][j] = -1e30f;
        }

        float p[4][4];
#pragma unroll
        for (int i = 0; i < 4; i++) {
            float mrow = m_s[ty*4+i];
            float lrow = li_s[ty*4+i];
#pragma unroll
            for (int j = 0; j < 4; j++)
                p[i][j] = __expf(s[i][j] - mrow) * lrow;
        }

        if (write_attn) {
#pragma unroll
            for (int i = 0; i < 4; i++) {
                size_t base = ((size_t)bh*NS + qt*64 + ty*4 + i)*NS + kt*64 + tx*4;
                *(float4*)(attn + base) = make_float4(p[i][0], p[i][1], p[i][2], p[i][3]);
            }
        }

        __syncthreads();   // everyone done reading K tile
#pragma unroll
        for (int i = 0; i < 4; i++)
#pragma unroll
            for (int j = 0; j < 4; j++)
                KPs[ty*4+i][tx*4+j] = p[i][j];
        __syncthreads();

#pragma unroll 8
        for (int kk = 0; kk < 64; kk++) {
            float a[4], b[4];
#pragma unroll
            for (int i = 0; i < 4; i++) a[i] = KPs[ty*4+i][kk];
#pragma unroll
            for (int j = 0; j < 4; j++) b[j] = Vs[kk][tx*4+j];
#pragma unroll
            for (int i = 0; i < 4; i++)
#pragma unroll
                for (int j = 0; j < 4; j++) o[i][j] += a[i]*b[j];
        }
        __syncthreads();
    }

    // zero-fill masked (upper) attn region for this q-tile
    if (write_attn && qt < (NS/64 - 1)) {
        int c0 = (qt + 1) * 64;
        int ncols4 = (NS - c0) >> 2;
        float4 z = make_float4(0.f, 0.f, 0.f, 0.f);
        for (int idx = tid; idx < 64*ncols4; idx += 256) {
            int r = idx / ncols4;
            int c = (idx - r*ncols4) << 2;
            *(float4*)(attn + ((size_t)bh*NS + qt*64 + r)*NS + c0 + c) = z;
        }
    }

    // write context [B,S,D]
    const int bb = bh >> 4, h = bh & 15;
#pragma unroll
    for (int i = 0; i < 4; i++) {
        int srow = qt*64 + ty*4 + i;
        size_t base = ((size_t)bb*NS + srow)*ND + h*NDK + tx*4;
        *(float4*)(g_ctx + base) = make_float4(o[i][0], o[i][1], o[i][2], o[i][3]);
    }
}

// ---------------------------------------------------------------------------
extern "C" void kernel_launch(void* const* d_in, const int* in_sizes, int n_in,
                              void* d_out, int out_size)
{
    (void)in_sizes; (void)n_in;
    const float* q  = (const float*)d_in[0];
    const float* k  = (const float*)d_in[1];
    const float* v  = (const float*)d_in[2];
    // d_in[3] = mask: causal tril, applied analytically
    const float* wq = (const float*)d_in[4];
    const float* bq = (const float*)d_in[5];
    const float* wk = (const float*)d_in[6];
    const float* bk = (const float*)d_in[7];
    const float* wv = (const float*)d_in[8];
    const float* bv = (const float*)d_in[9];
    const float* wo = (const float*)d_in[10];
    const float* bo = (const float*)d_in[11];
    float* out = (float*)d_out;

    const long long OUT_ELEMS  = (long long)NM * ND;          // 8388608
    const long long ATTN_ELEMS = (long long)NBH * NS * NS;    // 268435456

    float *Qd, *Kd, *Vd, *Ctx, *Outd;
    cudaGetSymbolAddress((void**)&Qd,  g_Q);
    cudaGetSymbolAddress((void**)&Kd,  g_K);
    cudaGetSymbolAddress((void**)&Vd,  g_V);
    cudaGetSymbolAddress((void**)&Ctx, g_ctx);
    cudaGetSymbolAddress((void**)&Outd, g_out);

    float* outp  = out;
    float* attnp = nullptr;
    if ((long long)out_size >= OUT_ELEMS + ATTN_ELEMS) {
        attnp = out + OUT_ELEMS;                 // [output | attn]
    } else if ((long long)out_size == ATTN_ELEMS) {
        attnp = out;                             // attn only
        outp  = Outd;
    }

    cudaFuncSetAttribute(attn_av_kernel,
                         cudaFuncAttributeMaxDynamicSharedMemorySize,
                         3*64*65*(int)sizeof(float));

    dim3 ggrid(ND/128, NM/128);
    gemm_xwT<1><<<ggrid, 256>>>(q, wq, bq, Qd, 0.125f);   // fold 1/sqrt(Dk)
    gemm_xwT<1><<<ggrid, 256>>>(k, wk, bk, Kd, 1.0f);
    gemm_xwT<1><<<ggrid, 256>>>(v, wv, bv, Vd, 1.0f);

    dim3 agrid(NS/64, NBH);
    attn_ml_kernel<<<agrid, 256>>>();
    attn_av_kernel<<<agrid, 256, 3*64*65*sizeof(float)>>>(attnp, attnp ? 1 : 0);

    gemm_xwT<0><<<ggrid, 256>>>(Ctx, wo, bo, outp, 1.0f);
}

// round 3
// speedup vs baseline: 1.4592x; 1.4592x over previous
#include <cuda_runtime.h>
#include <cstdint>

#define NB 4
#define NS 2048
#define ND 1024
#define NH 16
#define NDK 64
#define NBH (NB*NH)   /* 64 */
#define NM (NB*NS)    /* 8192 */

// Scratch (allocation-free: __device__ globals)
__device__ float g_Q[NBH*NS*NDK];
__device__ float g_K[NBH*NS*NDK];
__device__ float g_V[NBH*NS*NDK];
__device__ float g_ctx[(size_t)NM*ND];
__device__ float g_out[(size_t)NM*ND];
__device__ float g_m[NBH*NS];
__device__ float g_l[NBH*NS];

// ===========================================================================
// helpers
// ===========================================================================
__device__ __forceinline__ uint32_t smem_u32(const void* p) {
    uint32_t a;
    asm("{ .reg .u64 t; cvta.to.shared.u64 t, %1; cvt.u32.u64 %0, t; }"
        : "=r"(a) : "l"(p));
    return a;
}
__device__ __forceinline__ void sts128(uint32_t addr, uint32_t a, uint32_t b,
                                       uint32_t c, uint32_t d) {
    asm volatile("st.shared.v4.b32 [%0], {%1,%2,%3,%4};"
                 :: "r"(addr), "r"(a), "r"(b), "r"(c), "r"(d) : "memory");
}
#define LDSM_X4(r0, r1, r2, r3, addr) \
    asm volatile("ldmatrix.sync.aligned.m8n8.x4.shared.b16 {%0,%1,%2,%3}, [%4];" \
                 : "=r"(r0), "=r"(r1), "=r"(r2), "=r"(r3) : "r"(addr))

__device__ __forceinline__ void mma_bf16(float* d, const uint32_t* a, const uint32_t* b) {
    asm volatile("mma.sync.aligned.m16n8k16.row.col.f32.bf16.bf16.f32 "
                 "{%0,%1,%2,%3}, {%4,%5,%6,%7}, {%8,%9}, {%0,%1,%2,%3};"
                 : "+f"(d[0]), "+f"(d[1]), "+f"(d[2]), "+f"(d[3])
                 : "r"(a[0]), "r"(a[1]), "r"(a[2]), "r"(a[3]),
                   "r"(b[0]), "r"(b[1]));
}

// pack two fp32 into bf16x2 (x0 -> low 16, x1 -> high 16)
__device__ __forceinline__ uint32_t bf16x2_pack(float x0, float x1) {
    uint32_t r;
    asm("cvt.rn.bf16x2.f32 %0, %1, %2;" : "=r"(r) : "f"(x1), "f"(x0));
    return r;
}
// split 2 floats into (hi bf16x2, lo bf16x2) where lo = x - float(hi)
__device__ __forceinline__ void split2(float x0, float x1, uint32_t& h, uint32_t& l) {
    h = bf16x2_pack(x0, x1);
    float h0 = __uint_as_float(h << 16);
    float h1 = __uint_as_float(h & 0xFFFF0000u);
    l = bf16x2_pack(x0 - h0, x1 - h1);
}
__device__ __forceinline__ uint32_t sw64(uint32_t off) {
    return off ^ ((off >> 3) & 0x30);
}

// ===========================================================================
// bf16 3-split tensor-core GEMM: C[m,n] = sum_k A[m,k]*W[n,k]; (+bias)*scale
// MODE 0: C flat [M,1024]. MODE 1: C head-split [B,H,S,Dk].
// BM=64, BN=128, BK=32, 256 threads (8 warps, 2m x 4n), warp tile 32x32.
// ===========================================================================
#define AH_OFF 0u
#define AL_OFF 4096u
#define BH_OFF 8192u
#define BL_OFF 16384u

template<int MODE>
__global__ __launch_bounds__(256)
void gemm_mma(const float* __restrict__ A, const float* __restrict__ W,
              const float* __restrict__ bias, float* __restrict__ C, float scale)
{
    __shared__ __align__(1024) uint8_t sm[24576];
    const uint32_t sb = smem_u32(sm);

    const int tid  = threadIdx.x;
    const int wid  = tid >> 5, lane = tid & 31;
    const int m0 = blockIdx.y << 6;    // BM=64
    const int n0 = blockIdx.x << 7;    // BN=128
    const int mwOff = (wid & 1) * 32;
    const int nwOff = (wid >> 1) * 32;

    // loader assignment
    const int rowA = tid >> 2;           // 0..63
    const int segA = tid & 3;            // 0..3 (8 floats each)
    const int rowB0 = tid >> 2;          // 0..63
    const int rowB1 = (tid >> 2) + 64;   // 64..127
    const int segB = tid & 3;

    const uint32_t swA  = sw64((uint32_t)(rowA * 64 + segA * 16));
    const uint32_t swB0 = sw64((uint32_t)(rowB0 * 64 + segB * 16));
    const uint32_t swB1 = sw64((uint32_t)(rowB1 * 64 + segB * 16));

    float4 pa0, pa1, pb00, pb01, pb10, pb11;
    {
        const float* Ap = A + (size_t)(m0 + rowA) * ND + segA * 8;
        pa0 = *(const float4*)(Ap);
        pa1 = *(const float4*)(Ap + 4);
        const float* Bp0 = W + (size_t)(n0 + rowB0) * ND + segB * 8;
        pb00 = *(const float4*)(Bp0);
        pb01 = *(const float4*)(Bp0 + 4);
        const float* Bp1 = W + (size_t)(n0 + rowB1) * ND + segB * 8;
        pb10 = *(const float4*)(Bp1);
        pb11 = *(const float4*)(Bp1 + 4);
    }

    float d[2][4][4];
#pragma unroll
    for (int mt = 0; mt < 2; mt++)
#pragma unroll
        for (int nt = 0; nt < 4; nt++)
#pragma unroll
            for (int e = 0; e < 4; e++) d[mt][nt][e] = 0.f;

    // precomputed ldmatrix smem addresses (per lane)
    // A: row = mwOff + mt*16 + (lane&15), segIdx = ks*2 + (lane>>4)
    // B: row = nwOff + nt2*16 + (lane>>4)*8 + (lane&7), segIdx = ks*2 + ((lane>>3)&1)
    const int aRowL = (lane & 15);
    const int aSegL = (lane >> 4);
    const int bRowL = (lane >> 4) * 8 + (lane & 7);
    const int bSegL = (lane >> 3) & 1;

    for (int ch = 0; ch < 32; ch++) {
        __syncthreads();
        // split + store current chunk
        {
            uint32_t h0,h1,h2,h3,l0,l1,l2,l3;
            split2(pa0.x, pa0.y, h0, l0); split2(pa0.z, pa0.w, h1, l1);
            split2(pa1.x, pa1.y, h2, l2); split2(pa1.z, pa1.w, h3, l3);
            sts128(sb + AH_OFF + swA, h0, h1, h2, h3);
            sts128(sb + AL_OFF + swA, l0, l1, l2, l3);
            split2(pb00.x, pb00.y, h0, l0); split2(pb00.z, pb00.w, h1, l1);
            split2(pb01.x, pb01.y, h2, l2); split2(pb01.z, pb01.w, h3, l3);
            sts128(sb + BH_OFF + swB0, h0, h1, h2, h3);
            sts128(sb + BL_OFF + swB0, l0, l1, l2, l3);
            split2(pb10.x, pb10.y, h0, l0); split2(pb10.z, pb10.w, h1, l1);
            split2(pb11.x, pb11.y, h2, l2); split2(pb11.z, pb11.w, h3, l3);
            sts128(sb + BH_OFF + swB1, h0, h1, h2, h3);
            sts128(sb + BL_OFF + swB1, l0, l1, l2, l3);
        }
        __syncthreads();

        // prefetch next chunk
        if (ch < 31) {
            const int k0 = (ch + 1) * 32;
            const float* Ap = A + (size_t)(m0 + rowA) * ND + k0 + segA * 8;
            pa0 = *(const float4*)(Ap);
            pa1 = *(const float4*)(Ap + 4);
            const float* Bp0 = W + (size_t)(n0 + rowB0) * ND + k0 + segB * 8;
            pb00 = *(const float4*)(Bp0);
            pb01 = *(const float4*)(Bp0 + 4);
            const float* Bp1 = W + (size_t)(n0 + rowB1) * ND + k0 + segB * 8;
            pb10 = *(const float4*)(Bp1);
            pb11 = *(const float4*)(Bp1 + 4);
        }

        // compute: 2 k-steps of k16
#pragma unroll
        for (int ks = 0; ks < 2; ks++) {
            uint32_t aHi[2][4], aLo[2][4], bHi[2][4], bLo[2][4];
#pragma unroll
            for (int mt = 0; mt < 2; mt++) {
                uint32_t off = (uint32_t)((mwOff + mt*16 + aRowL) * 64
                                          + (ks*2 + aSegL) * 16);
                uint32_t sw = sw64(off);
                LDSM_X4(aHi[mt][0], aHi[mt][1], aHi[mt][2], aHi[mt][3], sb + AH_OFF + sw);
                LDSM_X4(aLo[mt][0], aLo[mt][1], aLo[mt][2], aLo[mt][3], sb + AL_OFF + sw);
            }
#pragma unroll
            for (int nt2 = 0; nt2 < 2; nt2++) {
                uint32_t off = (uint32_t)((nwOff + nt2*16 + bRowL) * 64
                                          + (ks*2 + bSegL) * 16);
                uint32_t sw = sw64(off);
                LDSM_X4(bHi[nt2][0], bHi[nt2][1], bHi[nt2][2], bHi[nt2][3], sb + BH_OFF + sw);
                LDSM_X4(bLo[nt2][0], bLo[nt2][1], bLo[nt2][2], bLo[nt2][3], sb + BL_OFF + sw);
            }
#pragma unroll
            for (int mt = 0; mt < 2; mt++) {
#pragma unroll
                for (int nt = 0; nt < 4; nt++) {
                    const uint32_t* bh = &bHi[nt >> 1][(nt & 1) * 2];
                    const uint32_t* bl = &bLo[nt >> 1][(nt & 1) * 2];
                    mma_bf16(d[mt][nt], aHi[mt], bh);
                    mma_bf16(d[mt][nt], aHi[mt], bl);
                    mma_bf16(d[mt][nt], aLo[mt], bh);
                }
            }
        }
    }

    // epilogue
    const int g = lane >> 2, tig = lane & 3;
#pragma unroll
    for (int mt = 0; mt < 2; mt++) {
#pragma unroll
        for (int nt = 0; nt < 4; nt++) {
            int col = n0 + nwOff + nt*8 + 2*tig;
            float2 bb = *(const float2*)&bias[col];
#pragma unroll
            for (int half = 0; half < 2; half++) {
                int row = m0 + mwOff + mt*16 + g + half*8;
                float2 o;
                o.x = (d[mt][nt][half*2+0] + bb.x) * scale;
                o.y = (d[mt][nt][half*2+1] + bb.y) * scale;
                if (MODE == 0) {
                    *(float2*)(C + (size_t)row * ND + col) = o;
                } else {
                    int bb2 = row >> 11;
                    int ss  = row & (NS - 1);
                    int h   = col >> 6;
                    int dd  = col & (NDK - 1);
                    *(float2*)(C + (((size_t)bb2*NH + h)*NS + ss)*NDK + dd) = o;
                }
            }
        }
    }
}

// ---------------------------------------------------------------------------
// Attention pass 1 (unchanged from passing R1 kernel)
// ---------------------------------------------------------------------------
__global__ __launch_bounds__(256)
void attn_ml_kernel()
{
    const int qt = blockIdx.x;
    const int bh = blockIdx.y;
    __shared__ float Qs[64][65];
    __shared__ float Ks[64][65];
    __shared__ float m_s[64];
    __shared__ float l_s[64];
    const int tid = threadIdx.x;
    const int tx = tid & 15, ty = tid >> 4;
    const float* Qg = g_Q + ((size_t)bh*NS + qt*64)*NDK;
    const float* Kg = g_K + (size_t)bh*NS*NDK;

#pragma unroll
    for (int u = 0; u < 4; u++) {
        int f = u*256 + tid;
        int r = f >> 4, c = (f & 15) << 2;
        float4 vv = *(const float4*)(Qg + r*NDK + c);
        Qs[r][c]=vv.x; Qs[r][c+1]=vv.y; Qs[r][c+2]=vv.z; Qs[r][c+3]=vv.w;
    }
    if (tid < 64) { m_s[tid] = -3.0e38f; l_s[tid] = 0.f; }
    __syncthreads();

    for (int kt = 0; kt <= qt; kt++) {
#pragma unroll
        for (int u = 0; u < 4; u++) {
            int f = u*256 + tid;
            int r = f >> 4, c = (f & 15) << 2;
            float4 vv = *(const float4*)(Kg + ((size_t)kt*64 + r)*NDK + c);
            Ks[r][c]=vv.x; Ks[r][c+1]=vv.y; Ks[r][c+2]=vv.z; Ks[r][c+3]=vv.w;
        }
        __syncthreads();

        float s[4][4];
#pragma unroll
        for (int i = 0; i < 4; i++)
#pragma unroll
            for (int j = 0; j < 4; j++) s[i][j] = 0.f;

#pragma unroll 8
        for (int d = 0; d < 64; d++) {
            float a[4], b[4];
#pragma unroll
            for (int i = 0; i < 4; i++) a[i] = Qs[ty*4+i][d];
#pragma unroll
            for (int j = 0; j < 4; j++) b[j] = Ks[tx*4+j][d];
#pragma unroll
            for (int i = 0; i < 4; i++)
#pragma unroll
                for (int j = 0; j < 4; j++) s[i][j] += a[i]*b[j];
        }

        if (kt == qt) {
#pragma unroll
            for (int i = 0; i < 4; i++)
#pragma unroll
                for (int j = 0; j < 4; j++)
                    if (ty*4+i < tx*4+j) s[i][j] = -1e30f;
        }

        float rmax[4];
#pragma unroll
        for (int i = 0; i < 4; i++) {
            rmax[i] = fmaxf(fmaxf(s[i][0], s[i][1]), fmaxf(s[i][2], s[i][3]));
#pragma unroll
            for (int o = 8; o > 0; o >>= 1)
                rmax[i] = fmaxf(rmax[i], __shfl_xor_sync(0xffffffffu, rmax[i], o));
        }
        if (tx == 0) {
#pragma unroll
            for (int i = 0; i < 4; i++) {
                int r = ty*4 + i;
                float mo = m_s[r];
                float mn = fmaxf(mo, rmax[i]);
                m_s[r] = mn;
                l_s[r] *= __expf(mo - mn);
            }
        }
        __syncthreads();

        float ps[4];
#pragma unroll
        for (int i = 0; i < 4; i++) {
            float mrow = m_s[ty*4+i];
            ps[i] = __expf(s[i][0]-mrow) + __expf(s[i][1]-mrow)
                  + __expf(s[i][2]-mrow) + __expf(s[i][3]-mrow);
#pragma unroll
            for (int o = 8; o > 0; o >>= 1)
                ps[i] += __shfl_xor_sync(0xffffffffu, ps[i], o);
        }
        if (tx == 0) {
#pragma unroll
            for (int i = 0; i < 4; i++) l_s[ty*4+i] += ps[i];
        }
        __syncthreads();
    }

    if (tid < 64) {
        g_m[(size_t)bh*NS + qt*64 + tid] = m_s[tid];
        g_l[(size_t)bh*NS + qt*64 + tid] = l_s[tid];
    }
}

// ---------------------------------------------------------------------------
// Attention pass 2 (unchanged from passing R1 kernel)
// ---------------------------------------------------------------------------
__global__ __launch_bounds__(256)
void attn_av_kernel(float* __restrict__ attn, int write_attn)
{
    extern __shared__ float dyn[];
    float (*Qs)[65]  = (float(*)[65])(dyn);
    float (*KPs)[65] = (float(*)[65])(dyn + 64*65);
    float (*Vs)[65]  = (float(*)[65])(dyn + 2*64*65);
    __shared__ float m_s[64];
    __shared__ float li_s[64];

    const int qt = blockIdx.x;
    const int bh = blockIdx.y;
    const int tid = threadIdx.x;
    const int tx = tid & 15, ty = tid >> 4;
    const float* Qg = g_Q + ((size_t)bh*NS + qt*64)*NDK;
    const float* Kg = g_K + (size_t)bh*NS*NDK;
    const float* Vg = g_V + (size_t)bh*NS*NDK;

#pragma unroll
    for (int u = 0; u < 4; u++) {
        int f = u*256 + tid;
        int r = f >> 4, c = (f & 15) << 2;
        float4 vv = *(const float4*)(Qg + r*NDK + c);
        Qs[r][c]=vv.x; Qs[r][c+1]=vv.y; Qs[r][c+2]=vv.z; Qs[r][c+3]=vv.w;
    }
    if (tid < 64) {
        m_s[tid]  = g_m[(size_t)bh*NS + qt*64 + tid];
        li_s[tid] = 1.0f / g_l[(size_t)bh*NS + qt*64 + tid];
    }
    __syncthreads();

    float o[4][4];
#pragma unroll
    for (int i = 0; i < 4; i++)
#pragma unroll
        for (int j = 0; j < 4; j++) o[i][j] = 0.f;

    for (int kt = 0; kt <= qt; kt++) {
#pragma unroll
        for (int u = 0; u < 4; u++) {
            int f = u*256 + tid;
            int r = f >> 4, c = (f & 15) << 2;
            float4 kv = *(const float4*)(Kg + ((size_t)kt*64 + r)*NDK + c);
            KPs[r][c]=kv.x; KPs[r][c+1]=kv.y; KPs[r][c+2]=kv.z; KPs[r][c+3]=kv.w;
            float4 vv = *(const float4*)(Vg + ((size_t)kt*64 + r)*NDK + c);
            Vs[r][c]=vv.x; Vs[r][c+1]=vv.y; Vs[r][c+2]=vv.z; Vs[r][c+3]=vv.w;
        }
        __syncthreads();

        float s[4][4];
#pragma unroll
        for (int i = 0; i < 4; i++)
#pragma unroll
            for (int j = 0; j < 4; j++) s[i][j] = 0.f;

#pragma unroll 8
        for (int d = 0; d < 64; d++) {
            float a[4], b[4];
#pragma unroll
            for (int i = 0; i < 4; i++) a[i] = Qs[ty*4+i][d];
#pragma unroll
            for (int j = 0; j < 4; j++) b[j] = KPs[tx*4+j][d];
#pragma unroll
            for (int i = 0; i < 4; i++)
#pragma unroll
                for (int j = 0; j < 4; j++) s[i][j] += a[i]*b[j];
        }

        if (kt == qt) {
#pragma unroll
            for (int i = 0; i < 4; i++)
#pragma unroll
                for (int j = 0; j < 4; j++)
                    if (ty*4+i < tx*4+j) s[i][j] = -1e30f;
        }

        float p[4][4];
#pragma unroll
        for (int i = 0; i < 4; i++) {
            float mrow = m_s[ty*4+i];
            float lrow = li_s[ty*4+i];
#pragma unroll
            for (int j = 0; j < 4; j++)
                p[i][j] = __expf(s[i][j] - mrow) * lrow;
        }

        if (write_attn) {
#pragma unroll
            for (int i = 0; i < 4; i++) {
                size_t base = ((size_t)bh*NS + qt*64 + ty*4 + i)*NS + kt*64 + tx*4;
                *(float4*)(attn + base) = make_float4(p[i][0], p[i][1], p[i][2], p[i][3]);
            }
        }

        __syncthreads();
#pragma unroll
        for (int i = 0; i < 4; i++)
#pragma unroll
            for (int j = 0; j < 4; j++)
                KPs[ty*4+i][tx*4+j] = p[i][j];
        __syncthreads();

#pragma unroll 8
        for (int kk = 0; kk < 64; kk++) {
            float a[4], b[4];
#pragma unroll
            for (int i = 0; i < 4; i++) a[i] = KPs[ty*4+i][kk];
#pragma unroll
            for (int j = 0; j < 4; j++) b[j] = Vs[kk][tx*4+j];
#pragma unroll
            for (int i = 0; i < 4; i++)
#pragma unroll
                for (int j = 0; j < 4; j++) o[i][j] += a[i]*b[j];
        }
        __syncthreads();
    }

    if (write_attn && qt < (NS/64 - 1)) {
        int c0 = (qt + 1) * 64;
        int ncols4 = (NS - c0) >> 2;
        float4 z = make_float4(0.f, 0.f, 0.f, 0.f);
        for (int idx = tid; idx < 64*ncols4; idx += 256) {
            int r = idx / ncols4;
            int c = (idx - r*ncols4) << 2;
            *(float4*)(attn + ((size_t)bh*NS + qt*64 + r)*NS + c0 + c) = z;
        }
    }

    const int bb = bh >> 4, h = bh & 15;
#pragma unroll
    for (int i = 0; i < 4; i++) {
        int srow = qt*64 + ty*4 + i;
        size_t base = ((size_t)bb*NS + srow)*ND + h*NDK + tx*4;
        *(float4*)(g_ctx + base) = make_float4(o[i][0], o[i][1], o[i][2], o[i][3]);
    }
}

// ---------------------------------------------------------------------------
extern "C" void kernel_launch(void* const* d_in, const int* in_sizes, int n_in,
                              void* d_out, int out_size)
{
    (void)in_sizes; (void)n_in;
    const float* q  = (const float*)d_in[0];
    const float* k  = (const float*)d_in[1];
    const float* v  = (const float*)d_in[2];
    const float* wq = (const float*)d_in[4];
    const float* bq = (const float*)d_in[5];
    const float* wk = (const float*)d_in[6];
    const float* bk = (const float*)d_in[7];
    const float* wv = (const float*)d_in[8];
    const float* bv = (const float*)d_in[9];
    const float* wo = (const float*)d_in[10];
    const float* bo = (const float*)d_in[11];
    float* out = (float*)d_out;

    const long long OUT_ELEMS  = (long long)NM * ND;
    const long long ATTN_ELEMS = (long long)NBH * NS * NS;

    float *Qd, *Kd, *Vd, *Ctx, *Outd;
    cudaGetSymbolAddress((void**)&Qd,  g_Q);
    cudaGetSymbolAddress((void**)&Kd,  g_K);
    cudaGetSymbolAddress((void**)&Vd,  g_V);
    cudaGetSymbolAddress((void**)&Ctx, g_ctx);
    cudaGetSymbolAddress((void**)&Outd, g_out);

    float* outp  = out;
    float* attnp = nullptr;
    if ((long long)out_size >= OUT_ELEMS + ATTN_ELEMS) {
        attnp = out + OUT_ELEMS;
    } else if ((long long)out_size == ATTN_ELEMS) {
        attnp = out;
        outp  = Outd;
    }

    cudaFuncSetAttribute(attn_av_kernel,
                         cudaFuncAttributeMaxDynamicSharedMemorySize,
                         3*64*65*(int)sizeof(float));

    dim3 ggrid(ND/128, NM/64);
    gemm_mma<1><<<ggrid, 256>>>(q, wq, bq, Qd, 0.125f);
    gemm_mma<1><<<ggrid, 256>>>(k, wk, bk, Kd, 1.0f);
    gemm_mma<1><<<ggrid, 256>>>(v, wv, bv, Vd, 1.0f);

    dim3 agrid(NS/64, NBH);
    attn_ml_kernel<<<agrid, 256>>>();
    attn_av_kernel<<<agrid, 256, 3*64*65*sizeof(float)>>>(attnp, attnp ? 1 : 0);

    gemm_mma<0><<<ggrid, 256>>>(Ctx, wo, bo, outp, 1.0f);
}

// round 4
// speedup vs baseline: 3.0917x; 2.1188x over previous
#include <cuda_runtime.h>
#include <cstdint>

#define NB 4
#define NS 2048
#define ND 1024
#define NH 16
#define NDK 64
#define NBH (NB*NH)   /* 64 */
#define NM (NB*NS)    /* 8192 */

#define PLB ((size_t)NBH*NS*128)   /* bytes per bf16 plane of one [BH,S,64] tensor */

// Scratch (allocation-free: __device__ globals)
__device__ __align__(128) uint8_t g_Qp[2*(size_t)NBH*NS*128];   // Qhi | Qlo
__device__ __align__(128) uint8_t g_KV[4*(size_t)NBH*NS*128];   // Khi | Klo | Vhi | Vlo
__device__ float g_ctx[(size_t)NM*ND];
__device__ float g_out[(size_t)NM*ND];
__device__ float g_m[NBH*NS];
__device__ float g_l[NBH*NS];

// ===========================================================================
// helpers
// ===========================================================================
__device__ __forceinline__ uint32_t smem_u32(const void* p) {
    uint32_t a;
    asm("{ .reg .u64 t; cvta.to.shared.u64 t, %1; cvt.u32.u64 %0, t; }"
        : "=r"(a) : "l"(p));
    return a;
}
__device__ __forceinline__ void sts128(uint32_t addr, uint32_t a, uint32_t b,
                                       uint32_t c, uint32_t d) {
    asm volatile("st.shared.v4.b32 [%0], {%1,%2,%3,%4};"
                 :: "r"(addr), "r"(a), "r"(b), "r"(c), "r"(d) : "memory");
}
#define LDSM_X4(r0, r1, r2, r3, addr) \
    asm volatile("ldmatrix.sync.aligned.m8n8.x4.shared.b16 {%0,%1,%2,%3}, [%4];" \
                 : "=r"(r0), "=r"(r1), "=r"(r2), "=r"(r3) : "r"(addr))
#define LDSM_X4T(r0, r1, r2, r3, addr) \
    asm volatile("ldmatrix.sync.aligned.m8n8.x4.trans.shared.b16 {%0,%1,%2,%3}, [%4];" \
                 : "=r"(r0), "=r"(r1), "=r"(r2), "=r"(r3) : "r"(addr))

__device__ __forceinline__ void mma_bf16(float* d, const uint32_t* a, const uint32_t* b) {
    asm volatile("mma.sync.aligned.m16n8k16.row.col.f32.bf16.bf16.f32 "
                 "{%0,%1,%2,%3}, {%4,%5,%6,%7}, {%8,%9}, {%0,%1,%2,%3};"
                 : "+f"(d[0]), "+f"(d[1]), "+f"(d[2]), "+f"(d[3])
                 : "r"(a[0]), "r"(a[1]), "r"(a[2]), "r"(a[3]),
                   "r"(b[0]), "r"(b[1]));
}

__device__ __forceinline__ uint32_t bf16x2_pack(float x0, float x1) {
    uint32_t r;
    asm("cvt.rn.bf16x2.f32 %0, %1, %2;" : "=r"(r) : "f"(x1), "f"(x0));
    return r;
}
__device__ __forceinline__ void split2(float x0, float x1, uint32_t& h, uint32_t& l) {
    h = bf16x2_pack(x0, x1);
    float h0 = __uint_as_float(h << 16);
    float h1 = __uint_as_float(h & 0xFFFF0000u);
    l = bf16x2_pack(x0 - h0, x1 - h1);
}
__device__ __forceinline__ uint32_t sw64(uint32_t off) {
    return off ^ ((off >> 3) & 0x30);
}
#define SW128(off) ((off) ^ (((off) >> 3) & 0x70))

__device__ __forceinline__ void cp16(uint32_t dst, const uint8_t* src) {
    asm volatile("{ .reg .u64 gp; cvta.to.global.u64 gp, %1; "
                 "cp.async.cg.shared.global [%0], [gp], 16; }"
                 :: "r"(dst), "l"(src));
}
#define CP_COMMIT() asm volatile("cp.async.commit_group;" ::: "memory")
#define CP_WAIT0()  asm volatile("cp.async.wait_group 0;" ::: "memory")
#define CP_WAIT1()  asm volatile("cp.async.wait_group 1;" ::: "memory")

// ===========================================================================
// bf16 3-split tensor-core GEMM (flat fp32 output) — final O projection.
// BM=64, BN=128, BK=32, 256 threads (8 warps, 2m x 4n), warp tile 32x32.
// ===========================================================================
#define AH_OFF 0u
#define AL_OFF 4096u
#define BH_OFF 8192u
#define BL_OFF 16384u

__global__ __launch_bounds__(256)
void gemm_mma(const float* __restrict__ A, const float* __restrict__ W,
              const float* __restrict__ bias, float* __restrict__ C)
{
    __shared__ __align__(1024) uint8_t sm[24576];
    const uint32_t sb = smem_u32(sm);

    const int tid  = threadIdx.x;
    const int wid  = tid >> 5, lane = tid & 31;
    const int m0 = blockIdx.y << 6;
    const int n0 = blockIdx.x << 7;
    const int mwOff = (wid & 1) * 32;
    const int nwOff = (wid >> 1) * 32;

    const int rowA = tid >> 2;
    const int segA = tid & 3;
    const int rowB0 = tid >> 2;
    const int rowB1 = (tid >> 2) + 64;
    const int segB = tid & 3;

    const uint32_t swA  = sw64((uint32_t)(rowA * 64 + segA * 16));
    const uint32_t swB0 = sw64((uint32_t)(rowB0 * 64 + segB * 16));
    const uint32_t swB1 = sw64((uint32_t)(rowB1 * 64 + segB * 16));

    float4 pa0, pa1, pb00, pb01, pb10, pb11;
    {
        const float* Ap = A + (size_t)(m0 + rowA) * ND + segA * 8;
        pa0 = *(const float4*)(Ap);
        pa1 = *(const float4*)(Ap + 4);
        const float* Bp0 = W + (size_t)(n0 + rowB0) * ND + segB * 8;
        pb00 = *(const float4*)(Bp0);
        pb01 = *(const float4*)(Bp0 + 4);
        const float* Bp1 = W + (size_t)(n0 + rowB1) * ND + segB * 8;
        pb10 = *(const float4*)(Bp1);
        pb11 = *(const float4*)(Bp1 + 4);
    }

    float d[2][4][4];
#pragma unroll
    for (int mt = 0; mt < 2; mt++)
#pragma unroll
        for (int nt = 0; nt < 4; nt++)
#pragma unroll
            for (int e = 0; e < 4; e++) d[mt][nt][e] = 0.f;

    const int aRowL = (lane & 15);
    const int aSegL = (lane >> 4);
    const int bRowL = (lane >> 4) * 8 + (lane & 7);
    const int bSegL = (lane >> 3) & 1;

    for (int ch = 0; ch < 32; ch++) {
        __syncthreads();
        {
            uint32_t h0,h1,h2,h3,l0,l1,l2,l3;
            split2(pa0.x, pa0.y, h0, l0); split2(pa0.z, pa0.w, h1, l1);
            split2(pa1.x, pa1.y, h2, l2); split2(pa1.z, pa1.w, h3, l3);
            sts128(sb + AH_OFF + swA, h0, h1, h2, h3);
            sts128(sb + AL_OFF + swA, l0, l1, l2, l3);
            split2(pb00.x, pb00.y, h0, l0); split2(pb00.z, pb00.w, h1, l1);
            split2(pb01.x, pb01.y, h2, l2); split2(pb01.z, pb01.w, h3, l3);
            sts128(sb + BH_OFF + swB0, h0, h1, h2, h3);
            sts128(sb + BL_OFF + swB0, l0, l1, l2, l3);
            split2(pb10.x, pb10.y, h0, l0); split2(pb10.z, pb10.w, h1, l1);
            split2(pb11.x, pb11.y, h2, l2); split2(pb11.z, pb11.w, h3, l3);
            sts128(sb + BH_OFF + swB1, h0, h1, h2, h3);
            sts128(sb + BL_OFF + swB1, l0, l1, l2, l3);
        }
        __syncthreads();

        if (ch < 31) {
            const int k0 = (ch + 1) * 32;
            const float* Ap = A + (size_t)(m0 + rowA) * ND + k0 + segA * 8;
            pa0 = *(const float4*)(Ap);
            pa1 = *(const float4*)(Ap + 4);
            const float* Bp0 = W + (size_t)(n0 + rowB0) * ND + k0 + segB * 8;
            pb00 = *(const float4*)(Bp0);
            pb01 = *(const float4*)(Bp0 + 4);
            const float* Bp1 = W + (size_t)(n0 + rowB1) * ND + k0 + segB * 8;
            pb10 = *(const float4*)(Bp1);
            pb11 = *(const float4*)(Bp1 + 4);
        }

#pragma unroll
        for (int ks = 0; ks < 2; ks++) {
            uint32_t aHi[2][4], aLo[2][4], bHi[2][4], bLo[2][4];
#pragma unroll
            for (int mt = 0; mt < 2; mt++) {
                uint32_t off = (uint32_t)((mwOff + mt*16 + aRowL) * 64
                                          + (ks*2 + aSegL) * 16);
                uint32_t sw = sw64(off);
                LDSM_X4(aHi[mt][0], aHi[mt][1], aHi[mt][2], aHi[mt][3], sb + AH_OFF + sw);
                LDSM_X4(aLo[mt][0], aLo[mt][1], aLo[mt][2], aLo[mt][3], sb + AL_OFF + sw);
            }
#pragma unroll
            for (int nt2 = 0; nt2 < 2; nt2++) {
                uint32_t off = (uint32_t)((nwOff + nt2*16 + bRowL) * 64
                                          + (ks*2 + bSegL) * 16);
                uint32_t sw = sw64(off);
                LDSM_X4(bHi[nt2][0], bHi[nt2][1], bHi[nt2][2], bHi[nt2][3], sb + BH_OFF + sw);
                LDSM_X4(bLo[nt2][0], bLo[nt2][1], bLo[nt2][2], bLo[nt2][3], sb + BL_OFF + sw);
            }
#pragma unroll
            for (int mt = 0; mt < 2; mt++) {
#pragma unroll
                for (int nt = 0; nt < 4; nt++) {
                    const uint32_t* bh = &bHi[nt >> 1][(nt & 1) * 2];
                    const uint32_t* bl = &bLo[nt >> 1][(nt & 1) * 2];
                    mma_bf16(d[mt][nt], aHi[mt], bh);
                    mma_bf16(d[mt][nt], aHi[mt], bl);
                    mma_bf16(d[mt][nt], aLo[mt], bh);
                }
            }
        }
    }

    const int g = lane >> 2, tig = lane & 3;
#pragma unroll
    for (int mt = 0; mt < 2; mt++) {
#pragma unroll
        for (int nt = 0; nt < 4; nt++) {
            int col = n0 + nwOff + nt*8 + 2*tig;
            float2 bb = *(const float2*)&bias[col];
#pragma unroll
            for (int half = 0; half < 2; half++) {
                int row = m0 + mwOff + mt*16 + g + half*8;
                float2 o;
                o.x = d[mt][nt][half*2+0] + bb.x;
                o.y = d[mt][nt][half*2+1] + bb.y;
                *(float2*)(C + (size_t)row * ND + col) = o;
            }
        }
    }
}

// ===========================================================================
// QKV projection GEMM: same mainloop, epilogue writes bf16 hi/lo planes
// into [BH][S][64] layout (128B rows). scale folded before split.
// ===========================================================================
__global__ __launch_bounds__(256)
void gemm_qkv(const float* __restrict__ A, const float* __restrict__ W,
              const float* __restrict__ bias, uint8_t* __restrict__ dst, float scale)
{
    __shared__ __align__(1024) uint8_t sm[24576];
    const uint32_t sb = smem_u32(sm);

    const int tid  = threadIdx.x;
    const int wid  = tid >> 5, lane = tid & 31;
    const int m0 = blockIdx.y << 6;
    const int n0 = blockIdx.x << 7;
    const int mwOff = (wid & 1) * 32;
    const int nwOff = (wid >> 1) * 32;

    const int rowA = tid >> 2;
    const int segA = tid & 3;
    const int rowB0 = tid >> 2;
    const int rowB1 = (tid >> 2) + 64;
    const int segB = tid & 3;

    const uint32_t swA  = sw64((uint32_t)(rowA * 64 + segA * 16));
    const uint32_t swB0 = sw64((uint32_t)(rowB0 * 64 + segB * 16));
    const uint32_t swB1 = sw64((uint32_t)(rowB1 * 64 + segB * 16));

    float4 pa0, pa1, pb00, pb01, pb10, pb11;
    {
        const float* Ap = A + (size_t)(m0 + rowA) * ND + segA * 8;
        pa0 = *(const float4*)(Ap);
        pa1 = *(const float4*)(Ap + 4);
        const float* Bp0 = W + (size_t)(n0 + rowB0) * ND + segB * 8;
        pb00 = *(const float4*)(Bp0);
        pb01 = *(const float4*)(Bp0 + 4);
        const float* Bp1 = W + (size_t)(n0 + rowB1) * ND + segB * 8;
        pb10 = *(const float4*)(Bp1);
        pb11 = *(const float4*)(Bp1 + 4);
    }

    float d[2][4][4];
#pragma unroll
    for (int mt = 0; mt < 2; mt++)
#pragma unroll
        for (int nt = 0; nt < 4; nt++)
#pragma unroll
            for (int e = 0; e < 4; e++) d[mt][nt][e] = 0.f;

    const int aRowL = (lane & 15);
    const int aSegL = (lane >> 4);
    const int bRowL = (lane >> 4) * 8 + (lane & 7);
    const int bSegL = (lane >> 3) & 1;

    for (int ch = 0; ch < 32; ch++) {
        __syncthreads();
        {
            uint32_t h0,h1,h2,h3,l0,l1,l2,l3;
            split2(pa0.x, pa0.y, h0, l0); split2(pa0.z, pa0.w, h1, l1);
            split2(pa1.x, pa1.y, h2, l2); split2(pa1.z, pa1.w, h3, l3);
            sts128(sb + AH_OFF + swA, h0, h1, h2, h3);
            sts128(sb + AL_OFF + swA, l0, l1, l2, l3);
            split2(pb00.x, pb00.y, h0, l0); split2(pb00.z, pb00.w, h1, l1);
            split2(pb01.x, pb01.y, h2, l2); split2(pb01.z, pb01.w, h3, l3);
            sts128(sb + BH_OFF + swB0, h0, h1, h2, h3);
            sts128(sb + BL_OFF + swB0, l0, l1, l2, l3);
            split2(pb10.x, pb10.y, h0, l0); split2(pb10.z, pb10.w, h1, l1);
            split2(pb11.x, pb11.y, h2, l2); split2(pb11.z, pb11.w, h3, l3);
            sts128(sb + BH_OFF + swB1, h0, h1, h2, h3);
            sts128(sb + BL_OFF + swB1, l0, l1, l2, l3);
        }
        __syncthreads();

        if (ch < 31) {
            const int k0 = (ch + 1) * 32;
            const float* Ap = A + (size_t)(m0 + rowA) * ND + k0 + segA * 8;
            pa0 = *(const float4*)(Ap);
            pa1 = *(const float4*)(Ap + 4);
            const float* Bp0 = W + (size_t)(n0 + rowB0) * ND + k0 + segB * 8;
            pb00 = *(const float4*)(Bp0);
            pb01 = *(const float4*)(Bp0 + 4);
            const float* Bp1 = W + (size_t)(n0 + rowB1) * ND + k0 + segB * 8;
            pb10 = *(const float4*)(Bp1);
            pb11 = *(const float4*)(Bp1 + 4);
        }

#pragma unroll
        for (int ks = 0; ks < 2; ks++) {
            uint32_t aHi[2][4], aLo[2][4], bHi[2][4], bLo[2][4];
#pragma unroll
            for (int mt = 0; mt < 2; mt++) {
                uint32_t off = (uint32_t)((mwOff + mt*16 + aRowL) * 64
                                          + (ks*2 + aSegL) * 16);
                uint32_t sw = sw64(off);
                LDSM_X4(aHi[mt][0], aHi[mt][1], aHi[mt][2], aHi[mt][3], sb + AH_OFF + sw);
                LDSM_X4(aLo[mt][0], aLo[mt][1], aLo[mt][2], aLo[mt][3], sb + AL_OFF + sw);
            }
#pragma unroll
            for (int nt2 = 0; nt2 < 2; nt2++) {
                uint32_t off = (uint32_t)((nwOff + nt2*16 + bRowL) * 64
                                          + (ks*2 + bSegL) * 16);
                uint32_t sw = sw64(off);
                LDSM_X4(bHi[nt2][0], bHi[nt2][1], bHi[nt2][2], bHi[nt2][3], sb + BH_OFF + sw);
                LDSM_X4(bLo[nt2][0], bLo[nt2][1], bLo[nt2][2], bLo[nt2][3], sb + BL_OFF + sw);
            }
#pragma unroll
            for (int mt = 0; mt < 2; mt++) {
#pragma unroll
                for (int nt = 0; nt < 4; nt++) {
                    const uint32_t* bh = &bHi[nt >> 1][(nt & 1) * 2];
                    const uint32_t* bl = &bLo[nt >> 1][(nt & 1) * 2];
                    mma_bf16(d[mt][nt], aHi[mt], bh);
                    mma_bf16(d[mt][nt], aHi[mt], bl);
                    mma_bf16(d[mt][nt], aLo[mt], bh);
                }
            }
        }
    }

    const int g = lane >> 2, tig = lane & 3;
#pragma unroll
    for (int mt = 0; mt < 2; mt++) {
#pragma unroll
        for (int nt = 0; nt < 4; nt++) {
            int col = n0 + nwOff + nt*8 + 2*tig;
            float2 bb = *(const float2*)&bias[col];
#pragma unroll
            for (int half = 0; half < 2; half++) {
                int row = m0 + mwOff + mt*16 + g + half*8;
                float ox = (d[mt][nt][half*2+0] + bb.x) * scale;
                float oy = (d[mt][nt][half*2+1] + bb.y) * scale;
                int bb2 = row >> 11;
                int ss  = row & (NS - 1);
                int hh  = col >> 6;
                int dd  = col & (NDK - 1);
                size_t boff = ((size_t)(bb2*NH + hh)*NS + ss)*128 + dd*2;
                uint32_t hi, lo;
                split2(ox, oy, hi, lo);
                *(uint32_t*)(dst + boff)       = hi;
                *(uint32_t*)(dst + PLB + boff) = lo;
            }
        }
    }
}

// ===========================================================================
// Attention pass 1: per (qb 128-row tile, bh): m,l stats via 3-split HMMA.
// 256 threads = 8 warps, warp = 16 rows x 64 cols per k-tile.
// dyn smem: Qh(16K) Ql(16K) | Kstage0(16K: Kh|Kl) | Kstage1(16K) = 64KB
// ===========================================================================
__global__ __launch_bounds__(256)
void attn_pass1(const uint8_t* __restrict__ Qp, const uint8_t* __restrict__ KV,
                float* __restrict__ gm, float* __restrict__ gl)
{
    extern __shared__ uint8_t smraw[];
    const uint32_t sb = smem_u32(smraw);
    const uint32_t QH = sb, QL = sb + 16384;
    const uint32_t KST = sb + 32768;

    const int qb = blockIdx.x, bh = blockIdx.y;
    const int tid = threadIdx.x, w = tid >> 5, lane = tid & 31;
    const int g = lane >> 2, tig = lane & 3;

    const uint8_t* Qg = Qp + (size_t)bh*NS*128 + (size_t)qb*128*128;
    const uint8_t* Kg = KV + (size_t)bh*NS*128;

    // Q tile: 2 planes x 128 rows x 128B
#pragma unroll
    for (int rr = 0; rr < 8; rr++) {
        int idx = rr*256 + tid;
        int pl = idx >> 10, wi = idx & 1023;
        int row = wi >> 3, chk = wi & 7;
        uint32_t off = (uint32_t)(row*128 + chk*16);
        cp16(QH + pl*16384 + SW128(off), Qg + (size_t)pl*PLB + off);
    }
    CP_COMMIT();
    // prologue: K tile 0
#pragma unroll
    for (int rr = 0; rr < 4; rr++) {
        int idx = rr*256 + tid;
        int pl = idx >> 9, wi = idx & 511;
        int row = wi >> 3, chk = wi & 7;
        uint32_t off = (uint32_t)(row*128 + chk*16);
        cp16(KST + pl*8192 + SW128(off), Kg + (size_t)pl*PLB + (size_t)row*128 + chk*16);
    }
    CP_COMMIT();
    CP_WAIT1();          // Q ready
    __syncthreads();

    uint32_t aQh[4][4], aQl[4][4];
#pragma unroll
    for (int ks = 0; ks < 4; ks++) {
        uint32_t off = (uint32_t)((w*16 + (lane & 15))*128 + ks*32 + (lane>>4)*16);
        uint32_t sw = SW128(off);
        LDSM_X4(aQh[ks][0], aQh[ks][1], aQh[ks][2], aQh[ks][3], QH + sw);
        LDSM_X4(aQl[ks][0], aQl[ks][1], aQl[ks][2], aQl[ks][3], QL + sw);
    }

    const int ntiles = 2*qb + 2;
    const int r0 = qb*128 + w*16 + g, r1 = r0 + 8;
    float m0 = -1e30f, m1 = -1e30f, l0 = 0.f, l1 = 0.f;

    for (int kt = 0; kt < ntiles; kt++) {
        if (kt + 1 < ntiles) {
            uint32_t st = KST + ((kt+1)&1)*16384;
#pragma unroll
            for (int rr = 0; rr < 4; rr++) {
                int idx = rr*256 + tid;
                int pl = idx >> 9, wi = idx & 511;
                int row = wi >> 3, chk = wi & 7;
                uint32_t off = (uint32_t)(row*128 + chk*16);
                cp16(st + pl*8192 + SW128(off),
                     Kg + (size_t)pl*PLB + (size_t)((kt+1)*64+row)*128 + chk*16);
            }
        }
        CP_COMMIT();
        CP_WAIT1();
        __syncthreads();

        const uint32_t KHs = KST + (kt&1)*16384, KLs = KHs + 8192;
        float c[8][4];
#pragma unroll
        for (int n8 = 0; n8 < 8; n8++)
#pragma unroll
            for (int e = 0; e < 4; e++) c[n8][e] = 0.f;

#pragma unroll
        for (int ks = 0; ks < 4; ks++) {
#pragma unroll
            for (int np = 0; np < 4; np++) {
                uint32_t off = (uint32_t)((np*16 + (lane>>4)*8 + (lane&7))*128
                                          + ks*32 + ((lane>>3)&1)*16);
                uint32_t sw = SW128(off);
                uint32_t bh4[4], bl4[4];
                LDSM_X4(bh4[0], bh4[1], bh4[2], bh4[3], KHs + sw);
                LDSM_X4(bl4[0], bl4[1], bl4[2], bl4[3], KLs + sw);
                mma_bf16(c[np*2],   aQh[ks], &bh4[0]);
                mma_bf16(c[np*2],   aQh[ks], &bl4[0]);
                mma_bf16(c[np*2],   aQl[ks], &bh4[0]);
                mma_bf16(c[np*2+1], aQh[ks], &bh4[2]);
                mma_bf16(c[np*2+1], aQh[ks], &bl4[2]);
                mma_bf16(c[np*2+1], aQl[ks], &bh4[2]);
            }
        }

        if (kt >= 2*qb) {
#pragma unroll
            for (int n8 = 0; n8 < 8; n8++) {
                int col = kt*64 + n8*8 + 2*tig;
                if (col   > r0) c[n8][0] = -1e30f;
                if (col+1 > r0) c[n8][1] = -1e30f;
                if (col   > r1) c[n8][2] = -1e30f;
                if (col+1 > r1) c[n8][3] = -1e30f;
            }
        }

        float tm0 = -1e30f, tm1 = -1e30f;
#pragma unroll
        for (int n8 = 0; n8 < 8; n8++) {
            tm0 = fmaxf(tm0, fmaxf(c[n8][0], c[n8][1]));
            tm1 = fmaxf(tm1, fmaxf(c[n8][2], c[n8][3]));
        }
        tm0 = fmaxf(tm0, __shfl_xor_sync(0xffffffffu, tm0, 1));
        tm0 = fmaxf(tm0, __shfl_xor_sync(0xffffffffu, tm0, 2));
        tm1 = fmaxf(tm1, __shfl_xor_sync(0xffffffffu, tm1, 1));
        tm1 = fmaxf(tm1, __shfl_xor_sync(0xffffffffu, tm1, 2));
        float mn0 = fmaxf(m0, tm0), mn1 = fmaxf(m1, tm1);
        float s0 = 0.f, s1 = 0.f;
#pragma unroll
        for (int n8 = 0; n8 < 8; n8++) {
            s0 += __expf(c[n8][0]-mn0) + __expf(c[n8][1]-mn0);
            s1 += __expf(c[n8][2]-mn1) + __expf(c[n8][3]-mn1);
        }
        s0 += __shfl_xor_sync(0xffffffffu, s0, 1);
        s0 += __shfl_xor_sync(0xffffffffu, s0, 2);
        s1 += __shfl_xor_sync(0xffffffffu, s1, 1);
        s1 += __shfl_xor_sync(0xffffffffu, s1, 2);
        l0 = l0*__expf(m0 - mn0) + s0;  m0 = mn0;
        l1 = l1*__expf(m1 - mn1) + s1;  m1 = mn1;
        __syncthreads();
    }

    if (tig == 0) {
        gm[(size_t)bh*NS + r0] = m0;  gl[(size_t)bh*NS + r0] = l0;
        gm[(size_t)bh*NS + r1] = m1;  gl[(size_t)bh*NS + r1] = l1;
    }
}

// ===========================================================================
// Attention pass 2: recompute S, p = exp(s-m)/l, write attn, O += P@V.
// dyn smem: Qh|Ql (32K) + 2 stages x (Kh|Kl|Vh|Vl = 32K) = 96KB
// ===========================================================================
__global__ __launch_bounds__(256)
void attn_pass2(const uint8_t* __restrict__ Qp, const uint8_t* __restrict__ KV,
                const float* __restrict__ gm, const float* __restrict__ gl,
                float* __restrict__ attn, float* __restrict__ ctx, int write_attn)
{
    extern __shared__ uint8_t smraw[];
    const uint32_t sb = smem_u32(smraw);
    const uint32_t QH = sb, QL = sb + 16384;
    const uint32_t ST = sb + 32768;

    const int qb = blockIdx.x, bh = blockIdx.y;
    const int tid = threadIdx.x, w = tid >> 5, lane = tid & 31;
    const int g = lane >> 2, tig = lane & 3;

    const uint8_t* Qg = Qp + (size_t)bh*NS*128 + (size_t)qb*128*128;
    const uint8_t* Kg = KV + (size_t)bh*NS*128;   // planes 0..3 = Kh,Kl,Vh,Vl

#pragma unroll
    for (int rr = 0; rr < 8; rr++) {
        int idx = rr*256 + tid;
        int pl = idx >> 10, wi = idx & 1023;
        int row = wi >> 3, chk = wi & 7;
        uint32_t off = (uint32_t)(row*128 + chk*16);
        cp16(QH + pl*16384 + SW128(off), Qg + (size_t)pl*PLB + off);
    }
    CP_COMMIT();
    // prologue: KV tile 0 (4 planes)
#pragma unroll
    for (int rr = 0; rr < 8; rr++) {
        int idx = rr*256 + tid;
        int pl = idx >> 9, wi = idx & 511;
        int row = wi >> 3, chk = wi & 7;
        uint32_t off = (uint32_t)(row*128 + chk*16);
        cp16(ST + pl*8192 + SW128(off), Kg + (size_t)pl*PLB + (size_t)row*128 + chk*16);
    }
    CP_COMMIT();
    CP_WAIT1();
    __syncthreads();

    uint32_t aQh[4][4], aQl[4][4];
#pragma unroll
    for (int ks = 0; ks < 4; ks++) {
        uint32_t off = (uint32_t)((w*16 + (lane & 15))*128 + ks*32 + (lane>>4)*16);
        uint32_t sw = SW128(off);
        LDSM_X4(aQh[ks][0], aQh[ks][1], aQh[ks][2], aQh[ks][3], QH + sw);
        LDSM_X4(aQl[ks][0], aQl[ks][1], aQl[ks][2], aQl[ks][3], QL + sw);
    }

    const int ntiles = 2*qb + 2;
    const int r0 = qb*128 + w*16 + g, r1 = r0 + 8;
    const float m0  = gm[(size_t)bh*NS + r0], m1 = gm[(size_t)bh*NS + r1];
    const float il0 = 1.0f / gl[(size_t)bh*NS + r0];
    const float il1 = 1.0f / gl[(size_t)bh*NS + r1];

    float oc[8][4];
#pragma unroll
    for (int n8 = 0; n8 < 8; n8++)
#pragma unroll
        for (int e = 0; e < 4; e++) oc[n8][e] = 0.f;

    for (int kt = 0; kt < ntiles; kt++) {
        if (kt + 1 < ntiles) {
            uint32_t st = ST + ((kt+1)&1)*32768;
#pragma unroll
            for (int rr = 0; rr < 8; rr++) {
                int idx = rr*256 + tid;
                int pl = idx >> 9, wi = idx & 511;
                int row = wi >> 3, chk = wi & 7;
                uint32_t off = (uint32_t)(row*128 + chk*16);
                cp16(st + pl*8192 + SW128(off),
                     Kg + (size_t)pl*PLB + (size_t)((kt+1)*64+row)*128 + chk*16);
            }
        }
        CP_COMMIT();
        CP_WAIT1();
        __syncthreads();

        const uint32_t B0 = ST + (kt&1)*32768;
        const uint32_t KHs = B0, KLs = B0 + 8192, VHs = B0 + 16384, VLs = B0 + 24576;

        float c[8][4];
#pragma unroll
        for (int n8 = 0; n8 < 8; n8++)
#pragma unroll
            for (int e = 0; e < 4; e++) c[n8][e] = 0.f;

#pragma unroll
        for (int ks = 0; ks < 4; ks++) {
#pragma unroll
            for (int np = 0; np < 4; np++) {
                uint32_t off = (uint32_t)((np*16 + (lane>>4)*8 + (lane&7))*128
                                          + ks*32 + ((lane>>3)&1)*16);
                uint32_t sw = SW128(off);
                uint32_t bh4[4], bl4[4];
                LDSM_X4(bh4[0], bh4[1], bh4[2], bh4[3], KHs + sw);
                LDSM_X4(bl4[0], bl4[1], bl4[2], bl4[3], KLs + sw);
                mma_bf16(c[np*2],   aQh[ks], &bh4[0]);
                mma_bf16(c[np*2],   aQh[ks], &bl4[0]);
                mma_bf16(c[np*2],   aQl[ks], &bh4[0]);
                mma_bf16(c[np*2+1], aQh[ks], &bh4[2]);
                mma_bf16(c[np*2+1], aQh[ks], &bl4[2]);
                mma_bf16(c[np*2+1], aQl[ks], &bh4[2]);
            }
        }

        if (kt >= 2*qb) {
#pragma unroll
            for (int n8 = 0; n8 < 8; n8++) {
                int col = kt*64 + n8*8 + 2*tig;
                if (col   > r0) c[n8][0] = -1e30f;
                if (col+1 > r0) c[n8][1] = -1e30f;
                if (col   > r1) c[n8][2] = -1e30f;
                if (col+1 > r1) c[n8][3] = -1e30f;
            }
        }

#pragma unroll
        for (int n8 = 0; n8 < 8; n8++) {
            c[n8][0] = __expf(c[n8][0]-m0)*il0;
            c[n8][1] = __expf(c[n8][1]-m0)*il0;
            c[n8][2] = __expf(c[n8][2]-m1)*il1;
            c[n8][3] = __expf(c[n8][3]-m1)*il1;
        }

        if (write_attn) {
            size_t ro0 = ((size_t)bh*NS + r0)*NS + (size_t)kt*64;
            size_t ro1 = ((size_t)bh*NS + r1)*NS + (size_t)kt*64;
#pragma unroll
            for (int n8 = 0; n8 < 8; n8++) {
                int col = n8*8 + 2*tig;
                *(float2*)(attn + ro0 + col) = make_float2(c[n8][0], c[n8][1]);
                *(float2*)(attn + ro1 + col) = make_float2(c[n8][2], c[n8][3]);
            }
        }

        // P @ V  (P fragments built from score fragments in registers)
#pragma unroll
        for (int ks = 0; ks < 4; ks++) {
            uint32_t pH[4], pL[4];
            split2(c[2*ks][0],   c[2*ks][1],   pH[0], pL[0]);
            split2(c[2*ks][2],   c[2*ks][3],   pH[1], pL[1]);
            split2(c[2*ks+1][0], c[2*ks+1][1], pH[2], pL[2]);
            split2(c[2*ks+1][2], c[2*ks+1][3], pH[3], pL[3]);
#pragma unroll
            for (int np = 0; np < 4; np++) {
                uint32_t off = (uint32_t)((ks*16 + ((lane>>3)&1)*8 + (lane&7))*128
                                          + np*32 + (lane>>4)*16);
                uint32_t sw = SW128(off);
                uint32_t vh4[4], vl4[4];
                LDSM_X4T(vh4[0], vh4[1], vh4[2], vh4[3], VHs + sw);
                LDSM_X4T(vl4[0], vl4[1], vl4[2], vl4[3], VLs + sw);
                mma_bf16(oc[np*2],   pH, &vh4[0]);
                mma_bf16(oc[np*2],   pH, &vl4[0]);
                mma_bf16(oc[np*2],   pL, &vh4[0]);
                mma_bf16(oc[np*2+1], pH, &vh4[2]);
                mma_bf16(oc[np*2+1], pH, &vl4[2]);
                mma_bf16(oc[np*2+1], pL, &vh4[2]);
            }
        }
        __syncthreads();
    }

    // write context [B,S,D]
    const int bb = bh >> 4, hh = bh & 15;
#pragma unroll
    for (int n8 = 0; n8 < 8; n8++) {
        int dk = n8*8 + 2*tig;
        *(float2*)(ctx + ((size_t)bb*NS + r0)*ND + hh*64 + dk) = make_float2(oc[n8][0], oc[n8][1]);
        *(float2*)(ctx + ((size_t)bb*NS + r1)*ND + hh*64 + dk) = make_float2(oc[n8][2], oc[n8][3]);
    }

    // zero-fill masked upper region for this q-tile
    if (write_attn && qb < (NS/128 - 1)) {
        int c0 = (qb + 1) * 128;
        int nv = (NS - c0) >> 2;
        float4 z = make_float4(0.f, 0.f, 0.f, 0.f);
        for (int idx = tid; idx < 128*nv; idx += 256) {
            int r = idx / nv;
            int cc = (idx - r*nv) << 2;
            *(float4*)(attn + ((size_t)bh*NS + qb*128 + r)*NS + c0 + cc) = z;
        }
    }
}

// ---------------------------------------------------------------------------
extern "C" void kernel_launch(void* const* d_in, const int* in_sizes, int n_in,
                              void* d_out, int out_size)
{
    (void)in_sizes; (void)n_in;
    const float* q  = (const float*)d_in[0];
    const float* k  = (const float*)d_in[1];
    const float* v  = (const float*)d_in[2];
    const float* wq = (const float*)d_in[4];
    const float* bq = (const float*)d_in[5];
    const float* wk = (const float*)d_in[6];
    const float* bk = (const float*)d_in[7];
    const float* wv = (const float*)d_in[8];
    const float* bv = (const float*)d_in[9];
    const float* wo = (const float*)d_in[10];
    const float* bo = (const float*)d_in[11];
    float* out = (float*)d_out;

    const long long OUT_ELEMS  = (long long)NM * ND;
    const long long ATTN_ELEMS = (long long)NBH * NS * NS;

    uint8_t *Qp, *KVp;
    float *Ctx, *Outd, *Md, *Ld;
    cudaGetSymbolAddress((void**)&Qp,  g_Qp);
    cudaGetSymbolAddress((void**)&KVp, g_KV);
    cudaGetSymbolAddress((void**)&Ctx, g_ctx);
    cudaGetSymbolAddress((void**)&Outd, g_out);
    cudaGetSymbolAddress((void**)&Md, g_m);
    cudaGetSymbolAddress((void**)&Ld, g_l);

    float* outp  = out;
    float* attnp = nullptr;
    if ((long long)out_size >= OUT_ELEMS + ATTN_ELEMS) {
        attnp = out + OUT_ELEMS;
    } else if ((long long)out_size == ATTN_ELEMS) {
        attnp = out;
        outp  = Outd;
    }

    cudaFuncSetAttribute(attn_pass1, cudaFuncAttributeMaxDynamicSharedMemorySize, 65536);
    cudaFuncSetAttribute(attn_pass2, cudaFuncAttributeMaxDynamicSharedMemorySize, 98304);

    dim3 ggrid(ND/128, NM/64);
    gemm_qkv<<<ggrid, 256>>>(q, wq, bq, Qp, 0.125f);
    gemm_qkv<<<ggrid, 256>>>(k, wk, bk, KVp, 1.0f);
    gemm_qkv<<<ggrid, 256>>>(v, wv, bv, KVp + 2*PLB, 1.0f);

    dim3 agrid(NS/128, NBH);
    attn_pass1<<<agrid, 256, 65536>>>(Qp, KVp, Md, Ld);
    attn_pass2<<<agrid, 256, 98304>>>(Qp, KVp, Md, Ld, attnp, Ctx, attnp ? 1 : 0);

    gemm_mma<<<ggrid, 256>>>(Ctx, wo, bo, outp);
}

// round 5
// speedup vs baseline: 3.5044x; 1.1335x over previous
#include <cuda_runtime.h>
#include <cstdint>

#define NB 4
#define NS 2048
#define ND 1024
#define NH 16
#define NDK 64
#define NBH (NB*NH)   /* 64 */
#define NM (NB*NS)    /* 8192 */

#define PLB ((size_t)NBH*NS*128)   /* bytes per 16-bit plane of one [BH,S,64] tensor */

// Scratch (allocation-free: __device__ globals)
__device__ __align__(128) uint8_t g_Qp[2*(size_t)NBH*NS*128];   // Qhi | Qlo (fp16)
__device__ __align__(128) uint8_t g_KV[2*(size_t)NBH*NS*128];   // K | V (fp16 single)
__device__ float g_ctx[(size_t)NM*ND];
__device__ float g_out[(size_t)NM*ND];
__device__ float g_m[NBH*NS];
__device__ float g_l[NBH*NS];

// ===========================================================================
// helpers
// ===========================================================================
__device__ __forceinline__ uint32_t smem_u32(const void* p) {
    uint32_t a;
    asm("{ .reg .u64 t; cvta.to.shared.u64 t, %1; cvt.u32.u64 %0, t; }"
        : "=r"(a) : "l"(p));
    return a;
}
__device__ __forceinline__ void sts128(uint32_t addr, uint32_t a, uint32_t b,
                                       uint32_t c, uint32_t d) {
    asm volatile("st.shared.v4.b32 [%0], {%1,%2,%3,%4};"
                 :: "r"(addr), "r"(a), "r"(b), "r"(c), "r"(d) : "memory");
}
#define LDSM_X4(r0, r1, r2, r3, addr) \
    asm volatile("ldmatrix.sync.aligned.m8n8.x4.shared.b16 {%0,%1,%2,%3}, [%4];" \
                 : "=r"(r0), "=r"(r1), "=r"(r2), "=r"(r3) : "r"(addr))
#define LDSM_X4T(r0, r1, r2, r3, addr) \
    asm volatile("ldmatrix.sync.aligned.m8n8.x4.trans.shared.b16 {%0,%1,%2,%3}, [%4];" \
                 : "=r"(r0), "=r"(r1), "=r"(r2), "=r"(r3) : "r"(addr))

__device__ __forceinline__ void mma_bf16(float* d, const uint32_t* a, const uint32_t* b) {
    asm volatile("mma.sync.aligned.m16n8k16.row.col.f32.bf16.bf16.f32 "
                 "{%0,%1,%2,%3}, {%4,%5,%6,%7}, {%8,%9}, {%0,%1,%2,%3};"
                 : "+f"(d[0]), "+f"(d[1]), "+f"(d[2]), "+f"(d[3])
                 : "r"(a[0]), "r"(a[1]), "r"(a[2]), "r"(a[3]),
                   "r"(b[0]), "r"(b[1]));
}
__device__ __forceinline__ void mma_f16(float* d, const uint32_t* a, const uint32_t* b) {
    asm volatile("mma.sync.aligned.m16n8k16.row.col.f32.f16.f16.f32 "
                 "{%0,%1,%2,%3}, {%4,%5,%6,%7}, {%8,%9}, {%0,%1,%2,%3};"
                 : "+f"(d[0]), "+f"(d[1]), "+f"(d[2]), "+f"(d[3])
                 : "r"(a[0]), "r"(a[1]), "r"(a[2]), "r"(a[3]),
                   "r"(b[0]), "r"(b[1]));
}

__device__ __forceinline__ uint32_t bf16x2_pack(float x0, float x1) {
    uint32_t r;
    asm("cvt.rn.bf16x2.f32 %0, %1, %2;" : "=r"(r) : "f"(x1), "f"(x0));
    return r;
}
__device__ __forceinline__ void split2(float x0, float x1, uint32_t& h, uint32_t& l) {
    h = bf16x2_pack(x0, x1);
    float h0 = __uint_as_float(h << 16);
    float h1 = __uint_as_float(h & 0xFFFF0000u);
    l = bf16x2_pack(x0 - h0, x1 - h1);
}
__device__ __forceinline__ uint32_t f16x2_pack(float x0, float x1) {
    uint32_t r;
    asm("cvt.rn.f16x2.f32 %0, %1, %2;" : "=r"(r) : "f"(x1), "f"(x0));
    return r;
}
__device__ __forceinline__ void split2h(float x0, float x1, uint32_t& h, uint32_t& l) {
    h = f16x2_pack(x0, x1);
    float h0, h1;
    asm("{ .reg .b16 a,b; mov.b32 {a,b}, %2; cvt.f32.f16 %0, a; cvt.f32.f16 %1, b; }"
        : "=f"(h0), "=f"(h1) : "r"(h));
    l = f16x2_pack(x0 - h0, x1 - h1);
}
__device__ __forceinline__ uint32_t sw64(uint32_t off) {
    return off ^ ((off >> 3) & 0x30);
}
#define SW128(off) ((off) ^ (((off) >> 3) & 0x70))

__device__ __forceinline__ void cp16(uint32_t dst, const uint8_t* src) {
    asm volatile("{ .reg .u64 gp; cvta.to.global.u64 gp, %1; "
                 "cp.async.cg.shared.global [%0], [gp], 16; }"
                 :: "r"(dst), "l"(src));
}
#define CP_COMMIT() asm volatile("cp.async.commit_group;" ::: "memory")
#define CP_WAIT1()  asm volatile("cp.async.wait_group 1;" ::: "memory")

// ===========================================================================
// bf16 3-split tensor-core GEMM mainloop (shared by both GEMM kernels).
// BM=64, BN=128, BK=32, 256 threads (8 warps, 2m x 4n), warp tile 32x32.
// ===========================================================================
#define AH_OFF 0u
#define AL_OFF 4096u
#define BH_OFF 8192u
#define BL_OFF 16384u

// epilogue MODE: 0 = flat fp32 (+bias), 2 = fp16 hi/lo planes, 1 = fp16 single plane
template<int MODE>
__global__ __launch_bounds__(256)
void gemm_mma(const float* __restrict__ A, const float* __restrict__ W,
              const float* __restrict__ bias, void* __restrict__ Cout, float scale)
{
    __shared__ __align__(1024) uint8_t sm[24576];
    const uint32_t sb = smem_u32(sm);

    const int tid  = threadIdx.x;
    const int wid  = tid >> 5, lane = tid & 31;
    const int m0 = blockIdx.y << 6;
    const int n0 = blockIdx.x << 7;
    const int mwOff = (wid & 1) * 32;
    const int nwOff = (wid >> 1) * 32;

    const int rowA = tid >> 2;
    const int segA = tid & 3;
    const int rowB0 = tid >> 2;
    const int rowB1 = (tid >> 2) + 64;
    const int segB = tid & 3;

    const uint32_t swA  = sw64((uint32_t)(rowA * 64 + segA * 16));
    const uint32_t swB0 = sw64((uint32_t)(rowB0 * 64 + segB * 16));
    const uint32_t swB1 = sw64((uint32_t)(rowB1 * 64 + segB * 16));

    float4 pa0, pa1, pb00, pb01, pb10, pb11;
    {
        const float* Ap = A + (size_t)(m0 + rowA) * ND + segA * 8;
        pa0 = *(const float4*)(Ap);
        pa1 = *(const float4*)(Ap + 4);
        const float* Bp0 = W + (size_t)(n0 + rowB0) * ND + segB * 8;
        pb00 = *(const float4*)(Bp0);
        pb01 = *(const float4*)(Bp0 + 4);
        const float* Bp1 = W + (size_t)(n0 + rowB1) * ND + segB * 8;
        pb10 = *(const float4*)(Bp1);
        pb11 = *(const float4*)(Bp1 + 4);
    }

    float d[2][4][4];
#pragma unroll
    for (int mt = 0; mt < 2; mt++)
#pragma unroll
        for (int nt = 0; nt < 4; nt++)
#pragma unroll
            for (int e = 0; e < 4; e++) d[mt][nt][e] = 0.f;

    const int aRowL = (lane & 15);
    const int aSegL = (lane >> 4);
    const int bRowL = (lane >> 4) * 8 + (lane & 7);
    const int bSegL = (lane >> 3) & 1;

    for (int ch = 0; ch < 32; ch++) {
        __syncthreads();
        {
            uint32_t h0,h1,h2,h3,l0,l1,l2,l3;
            split2(pa0.x, pa0.y, h0, l0); split2(pa0.z, pa0.w, h1, l1);
            split2(pa1.x, pa1.y, h2, l2); split2(pa1.z, pa1.w, h3, l3);
            sts128(sb + AH_OFF + swA, h0, h1, h2, h3);
            sts128(sb + AL_OFF + swA, l0, l1, l2, l3);
            split2(pb00.x, pb00.y, h0, l0); split2(pb00.z, pb00.w, h1, l1);
            split2(pb01.x, pb01.y, h2, l2); split2(pb01.z, pb01.w, h3, l3);
            sts128(sb + BH_OFF + swB0, h0, h1, h2, h3);
            sts128(sb + BL_OFF + swB0, l0, l1, l2, l3);
            split2(pb10.x, pb10.y, h0, l0); split2(pb10.z, pb10.w, h1, l1);
            split2(pb11.x, pb11.y, h2, l2); split2(pb11.z, pb11.w, h3, l3);
            sts128(sb + BH_OFF + swB1, h0, h1, h2, h3);
            sts128(sb + BL_OFF + swB1, l0, l1, l2, l3);
        }
        __syncthreads();

        if (ch < 31) {
            const int k0 = (ch + 1) * 32;
            const float* Ap = A + (size_t)(m0 + rowA) * ND + k0 + segA * 8;
            pa0 = *(const float4*)(Ap);
            pa1 = *(const float4*)(Ap + 4);
            const float* Bp0 = W + (size_t)(n0 + rowB0) * ND + k0 + segB * 8;
            pb00 = *(const float4*)(Bp0);
            pb01 = *(const float4*)(Bp0 + 4);
            const float* Bp1 = W + (size_t)(n0 + rowB1) * ND + k0 + segB * 8;
            pb10 = *(const float4*)(Bp1);
            pb11 = *(const float4*)(Bp1 + 4);
        }

#pragma unroll
        for (int ks = 0; ks < 2; ks++) {
            uint32_t aHi[2][4], aLo[2][4], bHi[2][4], bLo[2][4];
#pragma unroll
            for (int mt = 0; mt < 2; mt++) {
                uint32_t off = (uint32_t)((mwOff + mt*16 + aRowL) * 64
                                          + (ks*2 + aSegL) * 16);
                uint32_t sw = sw64(off);
                LDSM_X4(aHi[mt][0], aHi[mt][1], aHi[mt][2], aHi[mt][3], sb + AH_OFF + sw);
                LDSM_X4(aLo[mt][0], aLo[mt][1], aLo[mt][2], aLo[mt][3], sb + AL_OFF + sw);
            }
#pragma unroll
            for (int nt2 = 0; nt2 < 2; nt2++) {
                uint32_t off = (uint32_t)((nwOff + nt2*16 + bRowL) * 64
                                          + (ks*2 + bSegL) * 16);
                uint32_t sw = sw64(off);
                LDSM_X4(bHi[nt2][0], bHi[nt2][1], bHi[nt2][2], bHi[nt2][3], sb + BH_OFF + sw);
                LDSM_X4(bLo[nt2][0], bLo[nt2][1], bLo[nt2][2], bLo[nt2][3], sb + BL_OFF + sw);
            }
#pragma unroll
            for (int mt = 0; mt < 2; mt++) {
#pragma unroll
                for (int nt = 0; nt < 4; nt++) {
                    const uint32_t* bh = &bHi[nt >> 1][(nt & 1) * 2];
                    const uint32_t* bl = &bLo[nt >> 1][(nt & 1) * 2];
                    mma_bf16(d[mt][nt], aHi[mt], bh);
                    mma_bf16(d[mt][nt], aHi[mt], bl);
                    mma_bf16(d[mt][nt], aLo[mt], bh);
                }
            }
        }
    }

    const int g = lane >> 2, tig = lane & 3;
#pragma unroll
    for (int mt = 0; mt < 2; mt++) {
#pragma unroll
        for (int nt = 0; nt < 4; nt++) {
            int col = n0 + nwOff + nt*8 + 2*tig;
            float2 bb = *(const float2*)&bias[col];
#pragma unroll
            for (int half = 0; half < 2; half++) {
                int row = m0 + mwOff + mt*16 + g + half*8;
                float ox = (d[mt][nt][half*2+0] + bb.x) * scale;
                float oy = (d[mt][nt][half*2+1] + bb.y) * scale;
                if (MODE == 0) {
                    *(float2*)((float*)Cout + (size_t)row * ND + col) = make_float2(ox, oy);
                } else {
                    int bb2 = row >> 11;
                    int ss  = row & (NS - 1);
                    int hh  = col >> 6;
                    int dd  = col & (NDK - 1);
                    size_t boff = ((size_t)(bb2*NH + hh)*NS + ss)*128 + dd*2;
                    uint8_t* dst = (uint8_t*)Cout;
                    if (MODE == 2) {
                        uint32_t hi, lo;
                        split2h(ox, oy, hi, lo);
                        *(uint32_t*)(dst + boff)       = hi;
                        *(uint32_t*)(dst + PLB + boff) = lo;
                    } else {
                        *(uint32_t*)(dst + boff) = f16x2_pack(ox, oy);
                    }
                }
            }
        }
    }
}

// ===========================================================================
// Attention pass 1: m,l stats. Q = fp16 hi/lo, K = fp16 single plane.
// 256 threads = 8 warps, warp = 16 rows x 64 cols per k-tile.
// dyn smem: Qh(16K) Ql(16K) | Kstage0(8K) | Kstage1(8K) = 48KB
// ===========================================================================
__global__ __launch_bounds__(256)
void attn_pass1(const uint8_t* __restrict__ Qp, const uint8_t* __restrict__ KV,
                float* __restrict__ gm, float* __restrict__ gl)
{
    extern __shared__ uint8_t smraw[];
    const uint32_t sb = smem_u32(smraw);
    const uint32_t QH = sb, QL = sb + 16384;
    const uint32_t KST = sb + 32768;

    const int qb = blockIdx.x, bh = blockIdx.y;
    const int tid = threadIdx.x, w = tid >> 5, lane = tid & 31;
    const int g = lane >> 2, tig = lane & 3;

    const uint8_t* Qg = Qp + (size_t)bh*NS*128 + (size_t)qb*128*128;
    const uint8_t* Kg = KV + (size_t)bh*NS*128;   // K plane

#pragma unroll
    for (int rr = 0; rr < 8; rr++) {
        int idx = rr*256 + tid;
        int pl = idx >> 10, wi = idx & 1023;
        int row = wi >> 3, chk = wi & 7;
        uint32_t off = (uint32_t)(row*128 + chk*16);
        cp16(QH + pl*16384 + SW128(off), Qg + (size_t)pl*PLB + off);
    }
    CP_COMMIT();
#pragma unroll
    for (int rr = 0; rr < 2; rr++) {
        int idx = rr*256 + tid;
        int row = idx >> 3, chk = idx & 7;
        uint32_t off = (uint32_t)(row*128 + chk*16);
        cp16(KST + SW128(off), Kg + off);
    }
    CP_COMMIT();
    CP_WAIT1();
    __syncthreads();

    uint32_t aQh[4][4], aQl[4][4];
#pragma unroll
    for (int ks = 0; ks < 4; ks++) {
        uint32_t off = (uint32_t)((w*16 + (lane & 15))*128 + ks*32 + (lane>>4)*16);
        uint32_t sw = SW128(off);
        LDSM_X4(aQh[ks][0], aQh[ks][1], aQh[ks][2], aQh[ks][3], QH + sw);
        LDSM_X4(aQl[ks][0], aQl[ks][1], aQl[ks][2], aQl[ks][3], QL + sw);
    }

    const int ntiles = 2*qb + 2;
    const int r0 = qb*128 + w*16 + g, r1 = r0 + 8;
    float m0 = -1e30f, m1 = -1e30f, l0 = 0.f, l1 = 0.f;

    for (int kt = 0; kt < ntiles; kt++) {
        if (kt + 1 < ntiles) {
            uint32_t st = KST + ((kt+1)&1)*8192;
#pragma unroll
            for (int rr = 0; rr < 2; rr++) {
                int idx = rr*256 + tid;
                int row = idx >> 3, chk = idx & 7;
                uint32_t off = (uint32_t)(row*128 + chk*16);
                cp16(st + SW128(off), Kg + (size_t)((kt+1)*64+row)*128 + chk*16);
            }
        }
        CP_COMMIT();
        CP_WAIT1();
        __syncthreads();

        const uint32_t KHs = KST + (kt&1)*8192;
        float c[8][4];
#pragma unroll
        for (int n8 = 0; n8 < 8; n8++)
#pragma unroll
            for (int e = 0; e < 4; e++) c[n8][e] = 0.f;

#pragma unroll
        for (int ks = 0; ks < 4; ks++) {
#pragma unroll
            for (int np = 0; np < 4; np++) {
                uint32_t off = (uint32_t)((np*16 + (lane>>4)*8 + (lane&7))*128
                                          + ks*32 + ((lane>>3)&1)*16);
                uint32_t sw = SW128(off);
                uint32_t bh4[4];
                LDSM_X4(bh4[0], bh4[1], bh4[2], bh4[3], KHs + sw);
                mma_f16(c[np*2],   aQh[ks], &bh4[0]);
                mma_f16(c[np*2],   aQl[ks], &bh4[0]);
                mma_f16(c[np*2+1], aQh[ks], &bh4[2]);
                mma_f16(c[np*2+1], aQl[ks], &bh4[2]);
            }
        }

        if (kt >= 2*qb) {
#pragma unroll
            for (int n8 = 0; n8 < 8; n8++) {
                int col = kt*64 + n8*8 + 2*tig;
                if (col   > r0) c[n8][0] = -1e30f;
                if (col+1 > r0) c[n8][1] = -1e30f;
                if (col   > r1) c[n8][2] = -1e30f;
                if (col+1 > r1) c[n8][3] = -1e30f;
            }
        }

        float tm0 = -1e30f, tm1 = -1e30f;
#pragma unroll
        for (int n8 = 0; n8 < 8; n8++) {
            tm0 = fmaxf(tm0, fmaxf(c[n8][0], c[n8][1]));
            tm1 = fmaxf(tm1, fmaxf(c[n8][2], c[n8][3]));
        }
        tm0 = fmaxf(tm0, __shfl_xor_sync(0xffffffffu, tm0, 1));
        tm0 = fmaxf(tm0, __shfl_xor_sync(0xffffffffu, tm0, 2));
        tm1 = fmaxf(tm1, __shfl_xor_sync(0xffffffffu, tm1, 1));
        tm1 = fmaxf(tm1, __shfl_xor_sync(0xffffffffu, tm1, 2));
        float mn0 = fmaxf(m0, tm0), mn1 = fmaxf(m1, tm1);
        float s0 = 0.f, s1 = 0.f;
#pragma unroll
        for (int n8 = 0; n8 < 8; n8++) {
            s0 += __expf(c[n8][0]-mn0) + __expf(c[n8][1]-mn0);
            s1 += __expf(c[n8][2]-mn1) + __expf(c[n8][3]-mn1);
        }
        s0 += __shfl_xor_sync(0xffffffffu, s0, 1);
        s0 += __shfl_xor_sync(0xffffffffu, s0, 2);
        s1 += __shfl_xor_sync(0xffffffffu, s1, 1);
        s1 += __shfl_xor_sync(0xffffffffu, s1, 2);
        l0 = l0*__expf(m0 - mn0) + s0;  m0 = mn0;
        l1 = l1*__expf(m1 - mn1) + s1;  m1 = mn1;
        __syncthreads();
    }

    if (tig == 0) {
        gm[(size_t)bh*NS + r0] = m0;  gl[(size_t)bh*NS + r0] = l0;
        gm[(size_t)bh*NS + r1] = m1;  gl[(size_t)bh*NS + r1] = l1;
    }
}

// ===========================================================================
// Attention pass 2: recompute S, p = exp(s-m)/l, write attn, O += P@V.
// Q fp16 hi/lo; K,V single fp16 planes; P split to fp16 hi/lo in regs.
// dyn smem: Qh|Ql (32K) + 2 stages x (K 8K | V 8K) = 64KB
// ===========================================================================
__global__ __launch_bounds__(256)
void attn_pass2(const uint8_t* __restrict__ Qp, const uint8_t* __restrict__ KV,
                const float* __restrict__ gm, const float* __restrict__ gl,
                float* __restrict__ attn, float* __restrict__ ctx, int write_attn)
{
    extern __shared__ uint8_t smraw[];
    const uint32_t sb = smem_u32(smraw);
    const uint32_t QH = sb, QL = sb + 16384;
    const uint32_t ST = sb + 32768;

    const int qb = blockIdx.x, bh = blockIdx.y;
    const int tid = threadIdx.x, w = tid >> 5, lane = tid & 31;
    const int g = lane >> 2, tig = lane & 3;

    const uint8_t* Qg = Qp + (size_t)bh*NS*128 + (size_t)qb*128*128;
    const uint8_t* Kg = KV + (size_t)bh*NS*128;   // plane 0 = K, plane 1 = V

#pragma unroll
    for (int rr = 0; rr < 8; rr++) {
        int idx = rr*256 + tid;
        int pl = idx >> 10, wi = idx & 1023;
        int row = wi >> 3, chk = wi & 7;
        uint32_t off = (uint32_t)(row*128 + chk*16);
        cp16(QH + pl*16384 + SW128(off), Qg + (size_t)pl*PLB + off);
    }
    CP_COMMIT();
#pragma unroll
    for (int rr = 0; rr < 4; rr++) {
        int idx = rr*256 + tid;
        int pl = idx >> 9, wi = idx & 511;
        int row = wi >> 3, chk = wi & 7;
        uint32_t off = (uint32_t)(row*128 + chk*16);
        cp16(ST + pl*8192 + SW128(off), Kg + (size_t)pl*PLB + off);
    }
    CP_COMMIT();
    CP_WAIT1();
    __syncthreads();

    uint32_t aQh[4][4], aQl[4][4];
#pragma unroll
    for (int ks = 0; ks < 4; ks++) {
        uint32_t off = (uint32_t)((w*16 + (lane & 15))*128 + ks*32 + (lane>>4)*16);
        uint32_t sw = SW128(off);
        LDSM_X4(aQh[ks][0], aQh[ks][1], aQh[ks][2], aQh[ks][3], QH + sw);
        LDSM_X4(aQl[ks][0], aQl[ks][1], aQl[ks][2], aQl[ks][3], QL + sw);
    }

    const int ntiles = 2*qb + 2;
    const int r0 = qb*128 + w*16 + g, r1 = r0 + 8;
    const float m0  = gm[(size_t)bh*NS + r0], m1 = gm[(size_t)bh*NS + r1];
    const float il0 = 1.0f / gl[(size_t)bh*NS + r0];
    const float il1 = 1.0f / gl[(size_t)bh*NS + r1];

    float oc[8][4];
#pragma unroll
    for (int n8 = 0; n8 < 8; n8++)
#pragma unroll
        for (int e = 0; e < 4; e++) oc[n8][e] = 0.f;

    for (int kt = 0; kt < ntiles; kt++) {
        if (kt + 1 < ntiles) {
            uint32_t st = ST + ((kt+1)&1)*16384;
#pragma unroll
            for (int rr = 0; rr < 4; rr++) {
                int idx = rr*256 + tid;
                int pl = idx >> 9, wi = idx & 511;
                int row = wi >> 3, chk = wi & 7;
                uint32_t off = (uint32_t)(row*128 + chk*16);
                cp16(st + pl*8192 + SW128(off),
                     Kg + (size_t)pl*PLB + (size_t)((kt+1)*64+row)*128 + chk*16);
            }
        }
        CP_COMMIT();
        CP_WAIT1();
        __syncthreads();

        const uint32_t B0 = ST + (kt&1)*16384;
        const uint32_t KHs = B0, VHs = B0 + 8192;

        float c[8][4];
#pragma unroll
        for (int n8 = 0; n8 < 8; n8++)
#pragma unroll
            for (int e = 0; e < 4; e++) c[n8][e] = 0.f;

#pragma unroll
        for (int ks = 0; ks < 4; ks++) {
#pragma unroll
            for (int np = 0; np < 4; np++) {
                uint32_t off = (uint32_t)((np*16 + (lane>>4)*8 + (lane&7))*128
                                          + ks*32 + ((lane>>3)&1)*16);
                uint32_t sw = SW128(off);
                uint32_t bh4[4];
                LDSM_X4(bh4[0], bh4[1], bh4[2], bh4[3], KHs + sw);
                mma_f16(c[np*2],   aQh[ks], &bh4[0]);
                mma_f16(c[np*2],   aQl[ks], &bh4[0]);
                mma_f16(c[np*2+1], aQh[ks], &bh4[2]);
                mma_f16(c[np*2+1], aQl[ks], &bh4[2]);
            }
        }

        if (kt >= 2*qb) {
#pragma unroll
            for (int n8 = 0; n8 < 8; n8++) {
                int col = kt*64 + n8*8 + 2*tig;
                if (col   > r0) c[n8][0] = -1e30f;
                if (col+1 > r0) c[n8][1] = -1e30f;
                if (col   > r1) c[n8][2] = -1e30f;
                if (col+1 > r1) c[n8][3] = -1e30f;
            }
        }

#pragma unroll
        for (int n8 = 0; n8 < 8; n8++) {
            c[n8][0] = __expf(c[n8][0]-m0)*il0;
            c[n8][1] = __expf(c[n8][1]-m0)*il0;
            c[n8][2] = __expf(c[n8][2]-m1)*il1;
            c[n8][3] = __expf(c[n8][3]-m1)*il1;
        }

        if (write_attn) {
            size_t ro0 = ((size_t)bh*NS + r0)*NS + (size_t)kt*64;
            size_t ro1 = ((size_t)bh*NS + r1)*NS + (size_t)kt*64;
#pragma unroll
            for (int n8 = 0; n8 < 8; n8++) {
                int col = n8*8 + 2*tig;
                *(float2*)(attn + ro0 + col) = make_float2(c[n8][0], c[n8][1]);
                *(float2*)(attn + ro1 + col) = make_float2(c[n8][2], c[n8][3]);
            }
        }

        // P @ V  (P split into fp16 hi/lo fragments in registers)
#pragma unroll
        for (int ks = 0; ks < 4; ks++) {
            uint32_t pH[4], pL[4];
            split2h(c[2*ks][0],   c[2*ks][1],   pH[0], pL[0]);
            split2h(c[2*ks][2],   c[2*ks][3],   pH[1], pL[1]);
            split2h(c[2*ks+1][0], c[2*ks+1][1], pH[2], pL[2]);
            split2h(c[2*ks+1][2], c[2*ks+1][3], pH[3], pL[3]);
#pragma unroll
            for (int np = 0; np < 4; np++) {
                uint32_t off = (uint32_t)((ks*16 + ((lane>>3)&1)*8 + (lane&7))*128
                                          + np*32 + (lane>>4)*16);
                uint32_t sw = SW128(off);
                uint32_t vh4[4];
                LDSM_X4T(vh4[0], vh4[1], vh4[2], vh4[3], VHs + sw);
                mma_f16(oc[np*2],   pH, &vh4[0]);
                mma_f16(oc[np*2],   pL, &vh4[0]);
                mma_f16(oc[np*2+1], pH, &vh4[2]);
                mma_f16(oc[np*2+1], pL, &vh4[2]);
            }
        }
        __syncthreads();
    }

    // write context [B,S,D]
    const int bb = bh >> 4, hh = bh & 15;
#pragma unroll
    for (int n8 = 0; n8 < 8; n8++) {
        int dk = n8*8 + 2*tig;
        *(float2*)(ctx + ((size_t)bb*NS + r0)*ND + hh*64 + dk) = make_float2(oc[n8][0], oc[n8][1]);
        *(float2*)(ctx + ((size_t)bb*NS + r1)*ND + hh*64 + dk) = make_float2(oc[n8][2], oc[n8][3]);
    }

    // zero-fill masked upper region for this q-tile
    if (write_attn && qb < (NS/128 - 1)) {
        int c0 = (qb + 1) * 128;
        int nv = (NS - c0) >> 2;
        float4 z = make_float4(0.f, 0.f, 0.f, 0.f);
        for (int idx = tid; idx < 128*nv; idx += 256) {
            int r = idx / nv;
            int cc = (idx - r*nv) << 2;
            *(float4*)(attn + ((size_t)bh*NS + qb*128 + r)*NS + c0 + cc) = z;
        }
    }
}

// ---------------------------------------------------------------------------
extern "C" void kernel_launch(void* const* d_in, const int* in_sizes, int n_in,
                              void* d_out, int out_size)
{
    (void)in_sizes; (void)n_in;
    const float* q  = (const float*)d_in[0];
    const float* k  = (const float*)d_in[1];
    const float* v  = (const float*)d_in[2];
    const float* wq = (const float*)d_in[4];
    const float* bq = (const float*)d_in[5];
    const float* wk = (const float*)d_in[6];
    const float* bk = (const float*)d_in[7];
    const float* wv = (const float*)d_in[8];
    const float* bv = (const float*)d_in[9];
    const float* wo = (const float*)d_in[10];
    const float* bo = (const float*)d_in[11];
    float* out = (float*)d_out;

    const long long OUT_ELEMS  = (long long)NM * ND;
    const long long ATTN_ELEMS = (long long)NBH * NS * NS;

    uint8_t *Qp, *KVp;
    float *Ctx, *Outd, *Md, *Ld;
    cudaGetSymbolAddress((void**)&Qp,  g_Qp);
    cudaGetSymbolAddress((void**)&KVp, g_KV);
    cudaGetSymbolAddress((void**)&Ctx, g_ctx);
    cudaGetSymbolAddress((void**)&Outd, g_out);
    cudaGetSymbolAddress((void**)&Md, g_m);
    cudaGetSymbolAddress((void**)&Ld, g_l);

    float* outp  = out;
    float* attnp = nullptr;
    if ((long long)out_size >= OUT_ELEMS + ATTN_ELEMS) {
        attnp = out + OUT_ELEMS;
    } else if ((long long)out_size == ATTN_ELEMS) {
        attnp = out;
        outp  = Outd;
    }

    cudaFuncSetAttribute(attn_pass1, cudaFuncAttributeMaxDynamicSharedMemorySize, 49152);
    cudaFuncSetAttribute(attn_pass2, cudaFuncAttributeMaxDynamicSharedMemorySize, 65536);

    dim3 ggrid(ND/128, NM/64);
    gemm_mma<2><<<ggrid, 256>>>(q, wq, bq, Qp, 0.125f);          // Q: fp16 hi/lo
    gemm_mma<1><<<ggrid, 256>>>(k, wk, bk, KVp, 1.0f);           // K: fp16
    gemm_mma<1><<<ggrid, 256>>>(v, wv, bv, KVp + PLB, 1.0f);     // V: fp16

    dim3 agrid(NS/128, NBH);
    attn_pass1<<<agrid, 256, 49152>>>(Qp, KVp, Md, Ld);
    attn_pass2<<<agrid, 256, 65536>>>(Qp, KVp, Md, Ld, attnp, Ctx, attnp ? 1 : 0);

    gemm_mma<0><<<ggrid, 256>>>(Ctx, wo, bo, outp, 1.0f);
}

// round 6
// speedup vs baseline: 3.9949x; 1.1400x over previous
#include <cuda_runtime.h>
#include <cstdint>

#define NB 4
#define NS 2048
#define ND 1024
#define NH 16
#define NDK 64
#define NBH (NB*NH)   /* 64 */
#define NM (NB*NS)    /* 8192 */

#define PLB ((size_t)NBH*NS*128)   /* bytes per 16-bit plane of one [BH,S,64] tensor */

// Scratch (allocation-free: __device__ globals)
__device__ __align__(128) uint8_t g_Qp[(size_t)NBH*NS*128];     // Q (fp16 single)
__device__ __align__(128) uint8_t g_KV[2*(size_t)NBH*NS*128];   // K | V (fp16 single)
__device__ float g_ctx[(size_t)NM*ND];
__device__ float g_out[(size_t)NM*ND];
__device__ float g_m[NBH*NS];
__device__ float g_l[NBH*NS];

// ===========================================================================
// helpers
// ===========================================================================
__device__ __forceinline__ uint32_t smem_u32(const void* p) {
    uint32_t a;
    asm("{ .reg .u64 t; cvta.to.shared.u64 t, %1; cvt.u32.u64 %0, t; }"
        : "=r"(a) : "l"(p));
    return a;
}
__device__ __forceinline__ void sts128(uint32_t addr, uint32_t a, uint32_t b,
                                       uint32_t c, uint32_t d) {
    asm volatile("st.shared.v4.b32 [%0], {%1,%2,%3,%4};"
                 :: "r"(addr), "r"(a), "r"(b), "r"(c), "r"(d) : "memory");
}
#define LDSM_X4(r0, r1, r2, r3, addr) \
    asm volatile("ldmatrix.sync.aligned.m8n8.x4.shared.b16 {%0,%1,%2,%3}, [%4];" \
                 : "=r"(r0), "=r"(r1), "=r"(r2), "=r"(r3) : "r"(addr))
#define LDSM_X4T(r0, r1, r2, r3, addr) \
    asm volatile("ldmatrix.sync.aligned.m8n8.x4.trans.shared.b16 {%0,%1,%2,%3}, [%4];" \
                 : "=r"(r0), "=r"(r1), "=r"(r2), "=r"(r3) : "r"(addr))

__device__ __forceinline__ void mma_bf16(float* d, const uint32_t* a, const uint32_t* b) {
    asm volatile("mma.sync.aligned.m16n8k16.row.col.f32.bf16.bf16.f32 "
                 "{%0,%1,%2,%3}, {%4,%5,%6,%7}, {%8,%9}, {%0,%1,%2,%3};"
                 : "+f"(d[0]), "+f"(d[1]), "+f"(d[2]), "+f"(d[3])
                 : "r"(a[0]), "r"(a[1]), "r"(a[2]), "r"(a[3]),
                   "r"(b[0]), "r"(b[1]));
}
__device__ __forceinline__ void mma_f16(float* d, const uint32_t* a, const uint32_t* b) {
    asm volatile("mma.sync.aligned.m16n8k16.row.col.f32.f16.f16.f32 "
                 "{%0,%1,%2,%3}, {%4,%5,%6,%7}, {%8,%9}, {%0,%1,%2,%3};"
                 : "+f"(d[0]), "+f"(d[1]), "+f"(d[2]), "+f"(d[3])
                 : "r"(a[0]), "r"(a[1]), "r"(a[2]), "r"(a[3]),
                   "r"(b[0]), "r"(b[1]));
}

__device__ __forceinline__ uint32_t bf16x2_pack(float x0, float x1) {
    uint32_t r;
    asm("cvt.rn.bf16x2.f32 %0, %1, %2;" : "=r"(r) : "f"(x1), "f"(x0));
    return r;
}
__device__ __forceinline__ void split2(float x0, float x1, uint32_t& h, uint32_t& l) {
    h = bf16x2_pack(x0, x1);
    float h0 = __uint_as_float(h << 16);
    float h1 = __uint_as_float(h & 0xFFFF0000u);
    l = bf16x2_pack(x0 - h0, x1 - h1);
}
__device__ __forceinline__ uint32_t f16x2_pack(float x0, float x1) {
    uint32_t r;
    asm("cvt.rn.f16x2.f32 %0, %1, %2;" : "=r"(r) : "f"(x1), "f"(x0));
    return r;
}
__device__ __forceinline__ void split2h(float x0, float x1, uint32_t& h, uint32_t& l) {
    h = f16x2_pack(x0, x1);
    float h0, h1;
    asm("{ .reg .b16 a,b; mov.b32 {a,b}, %2; cvt.f32.f16 %0, a; cvt.f32.f16 %1, b; }"
        : "=f"(h0), "=f"(h1) : "r"(h));
    l = f16x2_pack(x0 - h0, x1 - h1);
}
__device__ __forceinline__ uint32_t sw64(uint32_t off) {
    return off ^ ((off >> 3) & 0x30);
}
#define SW128(off) ((off) ^ (((off) >> 3) & 0x70))

__device__ __forceinline__ void cp16(uint32_t dst, const uint8_t* src) {
    asm volatile("{ .reg .u64 gp; cvta.to.global.u64 gp, %1; "
                 "cp.async.cg.shared.global [%0], [gp], 16; }"
                 :: "r"(dst), "l"(src));
}
#define CP_COMMIT() asm volatile("cp.async.commit_group;" ::: "memory")
#define CP_WAIT1()  asm volatile("cp.async.wait_group 1;" ::: "memory")

// ===========================================================================
// bf16 3-split tensor-core GEMM body (device-inlined, shared by 2 kernels).
// BM=64, BN=128, BK=32, 256 threads (8 warps, 2m x 4n), warp tile 32x32.
// MODE 0: fp32 flat [M,1024] (+bias). MODE 1: fp16 plane, head-split, *scale.
// ===========================================================================
#define AH_OFF 0u
#define AL_OFF 4096u
#define BH_OFF 8192u
#define BL_OFF 16384u

template<int MODE>
__device__ __forceinline__
void gemm_body(const float* __restrict__ A, const float* __restrict__ W,
               const float* __restrict__ bias, void* __restrict__ Cout,
               float scale, uint32_t sb)
{
    const int tid  = threadIdx.x;
    const int wid  = tid >> 5, lane = tid & 31;
    const int m0 = blockIdx.y << 6;
    const int n0 = blockIdx.x << 7;
    const int mwOff = (wid & 1) * 32;
    const int nwOff = (wid >> 1) * 32;

    const int rowA = tid >> 2;
    const int segA = tid & 3;
    const int rowB0 = tid >> 2;
    const int rowB1 = (tid >> 2) + 64;
    const int segB = tid & 3;

    const uint32_t swA  = sw64((uint32_t)(rowA * 64 + segA * 16));
    const uint32_t swB0 = sw64((uint32_t)(rowB0 * 64 + segB * 16));
    const uint32_t swB1 = sw64((uint32_t)(rowB1 * 64 + segB * 16));

    float4 pa0, pa1, pb00, pb01, pb10, pb11;
    {
        const float* Ap = A + (size_t)(m0 + rowA) * ND + segA * 8;
        pa0 = *(const float4*)(Ap);
        pa1 = *(const float4*)(Ap + 4);
        const float* Bp0 = W + (size_t)(n0 + rowB0) * ND + segB * 8;
        pb00 = *(const float4*)(Bp0);
        pb01 = *(const float4*)(Bp0 + 4);
        const float* Bp1 = W + (size_t)(n0 + rowB1) * ND + segB * 8;
        pb10 = *(const float4*)(Bp1);
        pb11 = *(const float4*)(Bp1 + 4);
    }

    float d[2][4][4];
#pragma unroll
    for (int mt = 0; mt < 2; mt++)
#pragma unroll
        for (int nt = 0; nt < 4; nt++)
#pragma unroll
            for (int e = 0; e < 4; e++) d[mt][nt][e] = 0.f;

    const int aRowL = (lane & 15);
    const int aSegL = (lane >> 4);
    const int bRowL = (lane >> 4) * 8 + (lane & 7);
    const int bSegL = (lane >> 3) & 1;

    for (int ch = 0; ch < 32; ch++) {
        __syncthreads();
        {
            uint32_t h0,h1,h2,h3,l0,l1,l2,l3;
            split2(pa0.x, pa0.y, h0, l0); split2(pa0.z, pa0.w, h1, l1);
            split2(pa1.x, pa1.y, h2, l2); split2(pa1.z, pa1.w, h3, l3);
            sts128(sb + AH_OFF + swA, h0, h1, h2, h3);
            sts128(sb + AL_OFF + swA, l0, l1, l2, l3);
            split2(pb00.x, pb00.y, h0, l0); split2(pb00.z, pb00.w, h1, l1);
            split2(pb01.x, pb01.y, h2, l2); split2(pb01.z, pb01.w, h3, l3);
            sts128(sb + BH_OFF + swB0, h0, h1, h2, h3);
            sts128(sb + BL_OFF + swB0, l0, l1, l2, l3);
            split2(pb10.x, pb10.y, h0, l0); split2(pb10.z, pb10.w, h1, l1);
            split2(pb11.x, pb11.y, h2, l2); split2(pb11.z, pb11.w, h3, l3);
            sts128(sb + BH_OFF + swB1, h0, h1, h2, h3);
            sts128(sb + BL_OFF + swB1, l0, l1, l2, l3);
        }
        __syncthreads();

        if (ch < 31) {
            const int k0 = (ch + 1) * 32;
            const float* Ap = A + (size_t)(m0 + rowA) * ND + k0 + segA * 8;
            pa0 = *(const float4*)(Ap);
            pa1 = *(const float4*)(Ap + 4);
            const float* Bp0 = W + (size_t)(n0 + rowB0) * ND + k0 + segB * 8;
            pb00 = *(const float4*)(Bp0);
            pb01 = *(const float4*)(Bp0 + 4);
            const float* Bp1 = W + (size_t)(n0 + rowB1) * ND + k0 + segB * 8;
            pb10 = *(const float4*)(Bp1);
            pb11 = *(const float4*)(Bp1 + 4);
        }

#pragma unroll
        for (int ks = 0; ks < 2; ks++) {
            uint32_t aHi[2][4], aLo[2][4], bHi[2][4], bLo[2][4];
#pragma unroll
            for (int mt = 0; mt < 2; mt++) {
                uint32_t off = (uint32_t)((mwOff + mt*16 + aRowL) * 64
                                          + (ks*2 + aSegL) * 16);
                uint32_t sw = sw64(off);
                LDSM_X4(aHi[mt][0], aHi[mt][1], aHi[mt][2], aHi[mt][3], sb + AH_OFF + sw);
                LDSM_X4(aLo[mt][0], aLo[mt][1], aLo[mt][2], aLo[mt][3], sb + AL_OFF + sw);
            }
#pragma unroll
            for (int nt2 = 0; nt2 < 2; nt2++) {
                uint32_t off = (uint32_t)((nwOff + nt2*16 + bRowL) * 64
                                          + (ks*2 + bSegL) * 16);
                uint32_t sw = sw64(off);
                LDSM_X4(bHi[nt2][0], bHi[nt2][1], bHi[nt2][2], bHi[nt2][3], sb + BH_OFF + sw);
                LDSM_X4(bLo[nt2][0], bLo[nt2][1], bLo[nt2][2], bLo[nt2][3], sb + BL_OFF + sw);
            }
#pragma unroll
            for (int mt = 0; mt < 2; mt++) {
#pragma unroll
                for (int nt = 0; nt < 4; nt++) {
                    const uint32_t* bh = &bHi[nt >> 1][(nt & 1) * 2];
                    const uint32_t* bl = &bLo[nt >> 1][(nt & 1) * 2];
                    mma_bf16(d[mt][nt], aHi[mt], bh);
                    mma_bf16(d[mt][nt], aHi[mt], bl);
                    mma_bf16(d[mt][nt], aLo[mt], bh);
                }
            }
        }
    }

    const int g = lane >> 2, tig = lane & 3;
#pragma unroll
    for (int mt = 0; mt < 2; mt++) {
#pragma unroll
        for (int nt = 0; nt < 4; nt++) {
            int col = n0 + nwOff + nt*8 + 2*tig;
            float2 bb = *(const float2*)&bias[col];
#pragma unroll
            for (int half = 0; half < 2; half++) {
                int row = m0 + mwOff + mt*16 + g + half*8;
                float ox = (d[mt][nt][half*2+0] + bb.x) * scale;
                float oy = (d[mt][nt][half*2+1] + bb.y) * scale;
                if (MODE == 0) {
                    *(float2*)((float*)Cout + (size_t)row * ND + col) = make_float2(ox, oy);
                } else {
                    int bb2 = row >> 11;
                    int ss  = row & (NS - 1);
                    int hh  = col >> 6;
                    int dd  = col & (NDK - 1);
                    size_t boff = ((size_t)(bb2*NH + hh)*NS + ss)*128 + dd*2;
                    *(uint32_t*)((uint8_t*)Cout + boff) = f16x2_pack(ox, oy);
                }
            }
        }
    }
}

// Fused Q/K/V projections (blockIdx.z selects matrix); all emit fp16 planes.
__global__ __launch_bounds__(256)
void gemm_qkv3(const float* __restrict__ q, const float* __restrict__ k,
               const float* __restrict__ v,
               const float* __restrict__ wq, const float* __restrict__ bq,
               const float* __restrict__ wk, const float* __restrict__ bk,
               const float* __restrict__ wv, const float* __restrict__ bv,
               uint8_t* __restrict__ Qp, uint8_t* __restrict__ KVp)
{
    __shared__ __align__(1024) uint8_t sm[24576];
    const uint32_t sb = smem_u32(sm);
    if (blockIdx.z == 0) {
        gemm_body<1>(q, wq, bq, Qp, 0.125f, sb);
    } else if (blockIdx.z == 1) {
        gemm_body<1>(k, wk, bk, KVp, 1.0f, sb);
    } else {
        gemm_body<1>(v, wv, bv, KVp + PLB, 1.0f, sb);
    }
}

// Final O projection (fp32 flat out)
__global__ __launch_bounds__(256)
void gemm_out(const float* __restrict__ A, const float* __restrict__ W,
              const float* __restrict__ bias, float* __restrict__ C)
{
    __shared__ __align__(1024) uint8_t sm[24576];
    const uint32_t sb = smem_u32(sm);
    gemm_body<0>(A, W, bias, C, 1.0f, sb);
}

// ===========================================================================
// Attention pass 1: m,l stats. Q,K single fp16 planes.
// 256 threads = 8 warps, warp = 16 rows x 64 cols per k-tile.
// dyn smem: Q(16K) | Kstage0(8K) | Kstage1(8K) = 32KB
// qb processed in DESCENDING order (heavy tiles first).
// ===========================================================================
__global__ __launch_bounds__(256)
void attn_pass1(const uint8_t* __restrict__ Qp, const uint8_t* __restrict__ KV,
                float* __restrict__ gm, float* __restrict__ gl)
{
    extern __shared__ uint8_t smraw[];
    const uint32_t sb = smem_u32(smraw);
    const uint32_t QH = sb;
    const uint32_t KST = sb + 16384;

    const int qb = gridDim.x - 1 - blockIdx.x;
    const int bh = blockIdx.y;
    const int tid = threadIdx.x, w = tid >> 5, lane = tid & 31;
    const int g = lane >> 2, tig = lane & 3;

    const uint8_t* Qg = Qp + (size_t)bh*NS*128 + (size_t)qb*128*128;
    const uint8_t* Kg = KV + (size_t)bh*NS*128;

#pragma unroll
    for (int rr = 0; rr < 4; rr++) {
        int idx = rr*256 + tid;
        int row = idx >> 3, chk = idx & 7;
        uint32_t off = (uint32_t)(row*128 + chk*16);
        cp16(QH + SW128(off), Qg + off);
    }
    CP_COMMIT();
#pragma unroll
    for (int rr = 0; rr < 2; rr++) {
        int idx = rr*256 + tid;
        int row = idx >> 3, chk = idx & 7;
        uint32_t off = (uint32_t)(row*128 + chk*16);
        cp16(KST + SW128(off), Kg + off);
    }
    CP_COMMIT();
    CP_WAIT1();
    __syncthreads();

    uint32_t aQh[4][4];
#pragma unroll
    for (int ks = 0; ks < 4; ks++) {
        uint32_t off = (uint32_t)((w*16 + (lane & 15))*128 + ks*32 + (lane>>4)*16);
        uint32_t sw = SW128(off);
        LDSM_X4(aQh[ks][0], aQh[ks][1], aQh[ks][2], aQh[ks][3], QH + sw);
    }

    const int ntiles = 2*qb + 2;
    const int r0 = qb*128 + w*16 + g, r1 = r0 + 8;
    float m0 = -1e30f, m1 = -1e30f, l0 = 0.f, l1 = 0.f;

    for (int kt = 0; kt < ntiles; kt++) {
        if (kt + 1 < ntiles) {
            uint32_t st = KST + ((kt+1)&1)*8192;
#pragma unroll
            for (int rr = 0; rr < 2; rr++) {
                int idx = rr*256 + tid;
                int row = idx >> 3, chk = idx & 7;
                uint32_t off = (uint32_t)(row*128 + chk*16);
                cp16(st + SW128(off), Kg + (size_t)((kt+1)*64+row)*128 + chk*16);
            }
        }
        CP_COMMIT();
        CP_WAIT1();
        __syncthreads();

        const uint32_t KHs = KST + (kt&1)*8192;
        float c[8][4];
#pragma unroll
        for (int n8 = 0; n8 < 8; n8++)
#pragma unroll
            for (int e = 0; e < 4; e++) c[n8][e] = 0.f;

#pragma unroll
        for (int ks = 0; ks < 4; ks++) {
#pragma unroll
            for (int np = 0; np < 4; np++) {
                uint32_t off = (uint32_t)((np*16 + (lane>>4)*8 + (lane&7))*128
                                          + ks*32 + ((lane>>3)&1)*16);
                uint32_t sw = SW128(off);
                uint32_t bh4[4];
                LDSM_X4(bh4[0], bh4[1], bh4[2], bh4[3], KHs + sw);
                mma_f16(c[np*2],   aQh[ks], &bh4[0]);
                mma_f16(c[np*2+1], aQh[ks], &bh4[2]);
            }
        }

        if (kt >= 2*qb) {
#pragma unroll
            for (int n8 = 0; n8 < 8; n8++) {
                int col = kt*64 + n8*8 + 2*tig;
                if (col   > r0) c[n8][0] = -1e30f;
                if (col+1 > r0) c[n8][1] = -1e30f;
                if (col   > r1) c[n8][2] = -1e30f;
                if (col+1 > r1) c[n8][3] = -1e30f;
            }
        }

        float tm0 = -1e30f, tm1 = -1e30f;
#pragma unroll
        for (int n8 = 0; n8 < 8; n8++) {
            tm0 = fmaxf(tm0, fmaxf(c[n8][0], c[n8][1]));
            tm1 = fmaxf(tm1, fmaxf(c[n8][2], c[n8][3]));
        }
        tm0 = fmaxf(tm0, __shfl_xor_sync(0xffffffffu, tm0, 1));
        tm0 = fmaxf(tm0, __shfl_xor_sync(0xffffffffu, tm0, 2));
        tm1 = fmaxf(tm1, __shfl_xor_sync(0xffffffffu, tm1, 1));
        tm1 = fmaxf(tm1, __shfl_xor_sync(0xffffffffu, tm1, 2));
        float mn0 = fmaxf(m0, tm0), mn1 = fmaxf(m1, tm1);
        float s0 = 0.f, s1 = 0.f;
#pragma unroll
        for (int n8 = 0; n8 < 8; n8++) {
            s0 += __expf(c[n8][0]-mn0) + __expf(c[n8][1]-mn0);
            s1 += __expf(c[n8][2]-mn1) + __expf(c[n8][3]-mn1);
        }
        s0 += __shfl_xor_sync(0xffffffffu, s0, 1);
        s0 += __shfl_xor_sync(0xffffffffu, s0, 2);
        s1 += __shfl_xor_sync(0xffffffffu, s1, 1);
        s1 += __shfl_xor_sync(0xffffffffu, s1, 2);
        l0 = l0*__expf(m0 - mn0) + s0;  m0 = mn0;
        l1 = l1*__expf(m1 - mn1) + s1;  m1 = mn1;
        __syncthreads();
    }

    if (tig == 0) {
        gm[(size_t)bh*NS + r0] = m0;  gl[(size_t)bh*NS + r0] = l0;
        gm[(size_t)bh*NS + r1] = m1;  gl[(size_t)bh*NS + r1] = l1;
    }
}

// ===========================================================================
// Attention pass 2: recompute S identically, p = exp(s-m)/l, write attn,
// O += P@V. Q,K,V single fp16; P split to fp16 hi/lo in regs.
// dyn smem: Q(16K) + 2 stages x (K 8K | V 8K) = 48KB
// ===========================================================================
__global__ __launch_bounds__(256)
void attn_pass2(const uint8_t* __restrict__ Qp, const uint8_t* __restrict__ KV,
                const float* __restrict__ gm, const float* __restrict__ gl,
                float* __restrict__ attn, float* __restrict__ ctx, int write_attn)
{
    extern __shared__ uint8_t smraw[];
    const uint32_t sb = smem_u32(smraw);
    const uint32_t QH = sb;
    const uint32_t ST = sb + 16384;

    const int qb = gridDim.x - 1 - blockIdx.x;
    const int bh = blockIdx.y;
    const int tid = threadIdx.x, w = tid >> 5, lane = tid & 31;
    const int g = lane >> 2, tig = lane & 3;

    const uint8_t* Qg = Qp + (size_t)bh*NS*128 + (size_t)qb*128*128;
    const uint8_t* Kg = KV + (size_t)bh*NS*128;   // plane 0 = K, plane 1 = V

#pragma unroll
    for (int rr = 0; rr < 4; rr++) {
        int idx = rr*256 + tid;
        int row = idx >> 3, chk = idx & 7;
        uint32_t off = (uint32_t)(row*128 + chk*16);
        cp16(QH + SW128(off), Qg + off);
    }
    CP_COMMIT();
#pragma unroll
    for (int rr = 0; rr < 4; rr++) {
        int idx = rr*256 + tid;
        int pl = idx >> 9, wi = idx & 511;
        int row = wi >> 3, chk = wi & 7;
        uint32_t off = (uint32_t)(row*128 + chk*16);
        cp16(ST + pl*8192 + SW128(off), Kg + (size_t)pl*PLB + off);
    }
    CP_COMMIT();
    CP_WAIT1();
    __syncthreads();

    uint32_t aQh[4][4];
#pragma unroll
    for (int ks = 0; ks < 4; ks++) {
        uint32_t off = (uint32_t)((w*16 + (lane & 15))*128 + ks*32 + (lane>>4)*16);
        uint32_t sw = SW128(off);
        LDSM_X4(aQh[ks][0], aQh[ks][1], aQh[ks][2], aQh[ks][3], QH + sw);
    }

    const int ntiles = 2*qb + 2;
    const int r0 = qb*128 + w*16 + g, r1 = r0 + 8;
    const float m0  = gm[(size_t)bh*NS + r0], m1 = gm[(size_t)bh*NS + r1];
    const float il0 = 1.0f / gl[(size_t)bh*NS + r0];
    const float il1 = 1.0f / gl[(size_t)bh*NS + r1];

    float oc[8][4];
#pragma unroll
    for (int n8 = 0; n8 < 8; n8++)
#pragma unroll
        for (int e = 0; e < 4; e++) oc[n8][e] = 0.f;

    for (int kt = 0; kt < ntiles; kt++) {
        if (kt + 1 < ntiles) {
            uint32_t st = ST + ((kt+1)&1)*16384;
#pragma unroll
            for (int rr = 0; rr < 4; rr++) {
                int idx = rr*256 + tid;
                int pl = idx >> 9, wi = idx & 511;
                int row = wi >> 3, chk = wi & 7;
                uint32_t off = (uint32_t)(row*128 + chk*16);
                cp16(st + pl*8192 + SW128(off),
                     Kg + (size_t)pl*PLB + (size_t)((kt+1)*64+row)*128 + chk*16);
            }
        }
        CP_COMMIT();
        CP_WAIT1();
        __syncthreads();

        const uint32_t B0 = ST + (kt&1)*16384;
        const uint32_t KHs = B0, VHs = B0 + 8192;

        float c[8][4];
#pragma unroll
        for (int n8 = 0; n8 < 8; n8++)
#pragma unroll
            for (int e = 0; e < 4; e++) c[n8][e] = 0.f;

#pragma unroll
        for (int ks = 0; ks < 4; ks++) {
#pragma unroll
            for (int np = 0; np < 4; np++) {
                uint32_t off = (uint32_t)((np*16 + (lane>>4)*8 + (lane&7))*128
                                          + ks*32 + ((lane>>3)&1)*16);
                uint32_t sw = SW128(off);
                uint32_t bh4[4];
                LDSM_X4(bh4[0], bh4[1], bh4[2], bh4[3], KHs + sw);
                mma_f16(c[np*2],   aQh[ks], &bh4[0]);
                mma_f16(c[np*2+1], aQh[ks], &bh4[2]);
            }
        }

        if (kt >= 2*qb) {
#pragma unroll
            for (int n8 = 0; n8 < 8; n8++) {
                int col = kt*64 + n8*8 + 2*tig;
                if (col   > r0) c[n8][0] = -1e30f;
                if (col+1 > r0) c[n8][1] = -1e30f;
                if (col   > r1) c[n8][2] = -1e30f;
                if (col+1 > r1) c[n8][3] = -1e30f;
            }
        }

#pragma unroll
        for (int n8 = 0; n8 < 8; n8++) {
            c[n8][0] = __expf(c[n8][0]-m0)*il0;
            c[n8][1] = __expf(c[n8][1]-m0)*il0;
            c[n8][2] = __expf(c[n8][2]-m1)*il1;
            c[n8][3] = __expf(c[n8][3]-m1)*il1;
        }

        if (write_attn) {
            size_t ro0 = ((size_t)bh*NS + r0)*NS + (size_t)kt*64;
            size_t ro1 = ((size_t)bh*NS + r1)*NS + (size_t)kt*64;
#pragma unroll
            for (int n8 = 0; n8 < 8; n8++) {
                int col = n8*8 + 2*tig;
                *(float2*)(attn + ro0 + col) = make_float2(c[n8][0], c[n8][1]);
                *(float2*)(attn + ro1 + col) = make_float2(c[n8][2], c[n8][3]);
            }
        }

        // P @ V  (P split into fp16 hi/lo fragments in registers)
#pragma unroll
        for (int ks = 0; ks < 4; ks++) {
            uint32_t pH[4], pL[4];
            split2h(c[2*ks][0],   c[2*ks][1],   pH[0], pL[0]);
            split2h(c[2*ks][2],   c[2*ks][3],   pH[1], pL[1]);
            split2h(c[2*ks+1][0], c[2*ks+1][1], pH[2], pL[2]);
            split2h(c[2*ks+1][2], c[2*ks+1][3], pH[3], pL[3]);
#pragma unroll
            for (int np = 0; np < 4; np++) {
                uint32_t off = (uint32_t)((ks*16 + ((lane>>3)&1)*8 + (lane&7))*128
                                          + np*32 + (lane>>4)*16);
                uint32_t sw = SW128(off);
                uint32_t vh4[4];
                LDSM_X4T(vh4[0], vh4[1], vh4[2], vh4[3], VHs + sw);
                mma_f16(oc[np*2],   pH, &vh4[0]);
                mma_f16(oc[np*2],   pL, &vh4[0]);
                mma_f16(oc[np*2+1], pH, &vh4[2]);
                mma_f16(oc[np*2+1], pL, &vh4[2]);
            }
        }
        __syncthreads();
    }

    // write context [B,S,D]
    const int bb = bh >> 4, hh = bh & 15;
#pragma unroll
    for (int n8 = 0; n8 < 8; n8++) {
        int dk = n8*8 + 2*tig;
        *(float2*)(ctx + ((size_t)bb*NS + r0)*ND + hh*64 + dk) = make_float2(oc[n8][0], oc[n8][1]);
        *(float2*)(ctx + ((size_t)bb*NS + r1)*ND + hh*64 + dk) = make_float2(oc[n8][2], oc[n8][3]);
    }

    // zero-fill masked upper region for this q-tile
    if (write_attn && qb < (NS/128 - 1)) {
        int c0 = (qb + 1) * 128;
        int nv = (NS - c0) >> 2;
        float4 z = make_float4(0.f, 0.f, 0.f, 0.f);
        for (int idx = tid; idx < 128*nv; idx += 256) {
            int r = idx / nv;
            int cc = (idx - r*nv) << 2;
            *(float4*)(attn + ((size_t)bh*NS + qb*128 + r)*NS + c0 + cc) = z;
        }
    }
}

// ---------------------------------------------------------------------------
extern "C" void kernel_launch(void* const* d_in, const int* in_sizes, int n_in,
                              void* d_out, int out_size)
{
    (void)in_sizes; (void)n_in;
    const float* q  = (const float*)d_in[0];
    const float* k  = (const float*)d_in[1];
    const float* v  = (const float*)d_in[2];
    const float* wq = (const float*)d_in[4];
    const float* bq = (const float*)d_in[5];
    const float* wk = (const float*)d_in[6];
    const float* bk = (const float*)d_in[7];
    const float* wv = (const float*)d_in[8];
    const float* bv = (const float*)d_in[9];
    const float* wo = (const float*)d_in[10];
    const float* bo = (const float*)d_in[11];
    float* out = (float*)d_out;

    const long long OUT_ELEMS  = (long long)NM * ND;
    const long long ATTN_ELEMS = (long long)NBH * NS * NS;

    uint8_t *Qp, *KVp;
    float *Ctx, *Outd, *Md, *Ld;
    cudaGetSymbolAddress((void**)&Qp,  g_Qp);
    cudaGetSymbolAddress((void**)&KVp, g_KV);
    cudaGetSymbolAddress((void**)&Ctx, g_ctx);
    cudaGetSymbolAddress((void**)&Outd, g_out);
    cudaGetSymbolAddress((void**)&Md, g_m);
    cudaGetSymbolAddress((void**)&Ld, g_l);

    float* outp  = out;
    float* attnp = nullptr;
    if ((long long)out_size >= OUT_ELEMS + ATTN_ELEMS) {
        attnp = out + OUT_ELEMS;
    } else if ((long long)out_size == ATTN_ELEMS) {
        attnp = out;
        outp  = Outd;
    }

    cudaFuncSetAttribute(attn_pass1, cudaFuncAttributeMaxDynamicSharedMemorySize, 32768);
    cudaFuncSetAttribute(attn_pass2, cudaFuncAttributeMaxDynamicSharedMemorySize, 49152);

    dim3 ggrid(ND/128, NM/64, 3);
    gemm_qkv3<<<ggrid, 256>>>(q, k, v, wq, bq, wk, bk, wv, bv, Qp, KVp);

    dim3 agrid(NS/128, NBH);
    attn_pass1<<<agrid, 256, 32768>>>(Qp, KVp, Md, Ld);
    attn_pass2<<<agrid, 256, 49152>>>(Qp, KVp, Md, Ld, attnp, Ctx, attnp ? 1 : 0);

    dim3 ogrid(ND/128, NM/64);
    gemm_out<<<ogrid, 256>>>(Ctx, wo, bo, outp);
}